// round 2
// baseline (speedup 1.0000x reference)
#include <cuda_runtime.h>
#include <cuda_bf16.h>
#include <math.h>

// Problem dims (fixed by the reference)
#define TT 8192   // sequence length T
#define EE 4096   // embedding E

// ---------------- scratch (static device memory; no allocations) -------------
__device__ float g_q[(size_t)TT * EE];
__device__ float g_k[(size_t)TT * EE];
__device__ float g_v[(size_t)TT * EE];
__device__ float g_S[(size_t)EE * EE];
__device__ float g_o[(size_t)EE * TT];

// ---------------- generic tiled SGEMM ----------------------------------------
// C[M,N] = op(A) @ op(B) (+ bias[n]), all fp32, C row-major (ldc = N).
//  !TA: A stored [M,K] row-major;  TA: A stored [K,M] row-major (use A^T)
//  !TB: B stored [K,N] row-major;  TB: B stored [N,K] row-major (use B^T)
// All of M,N are multiples of 128 and K multiples of 16 in this problem,
// so no bounds checks.
constexpr int BM = 128, BN = 128, BK = 16, TM = 8, TN = 8;
constexpr int PAD = 4;

template <bool TA, bool TB, bool BIAS>
__global__ __launch_bounds__(256, 2)
void gemm_kernel(const float* __restrict__ A, const float* __restrict__ B,
                 const float* __restrict__ bias, float* __restrict__ C,
                 int M, int N, int K)
{
    __shared__ float As[BK][BM + PAD];
    __shared__ float Bs[BK][BN + PAD];

    const int bm = blockIdx.y * BM;
    const int bn = blockIdx.x * BN;
    const int tid = threadIdx.x;
    const int tx = tid & 15;       // 0..15 -> N direction
    const int ty = tid >> 4;       // 0..15 -> M direction

    float acc[TM][TN] = {};

    for (int k0 = 0; k0 < K; k0 += BK) {
        // ---- load A tile into As[k][m] ----
        if (!TA) {
            // A[M,K]: tile 128 rows x 16 k, contiguous along k. 512 float4s.
#pragma unroll
            for (int r = 0; r < 2; r++) {
                int m  = (tid >> 2) + r * 64;
                int kv = (tid & 3) * 4;
                float4 val = *reinterpret_cast<const float4*>(
                    &A[(size_t)(bm + m) * K + k0 + kv]);
                As[kv + 0][m] = val.x;
                As[kv + 1][m] = val.y;
                As[kv + 2][m] = val.z;
                As[kv + 3][m] = val.w;
            }
        } else {
            // A[K,M]: tile 16 k-rows x 128 m, contiguous along m.
#pragma unroll
            for (int r = 0; r < 2; r++) {
                int idx = tid + r * 256;     // float4 index
                int k   = idx >> 5;          // /32
                int mv  = (idx & 31) * 4;
                float4 val = *reinterpret_cast<const float4*>(
                    &A[(size_t)(k0 + k) * M + bm + mv]);
                *reinterpret_cast<float4*>(&As[k][mv]) = val;
            }
        }
        // ---- load B tile into Bs[k][n] ----
        if (!TB) {
            // B[K,N]: tile 16 k-rows x 128 n, contiguous along n.
#pragma unroll
            for (int r = 0; r < 2; r++) {
                int idx = tid + r * 256;
                int k   = idx >> 5;
                int nv  = (idx & 31) * 4;
                float4 val = *reinterpret_cast<const float4*>(
                    &B[(size_t)(k0 + k) * N + bn + nv]);
                *reinterpret_cast<float4*>(&Bs[k][nv]) = val;
            }
        } else {
            // B[N,K]: tile 128 n-rows x 16 k, contiguous along k.
#pragma unroll
            for (int r = 0; r < 2; r++) {
                int n  = (tid >> 2) + r * 64;
                int kv = (tid & 3) * 4;
                float4 val = *reinterpret_cast<const float4*>(
                    &B[(size_t)(bn + n) * K + k0 + kv]);
                Bs[kv + 0][n] = val.x;
                Bs[kv + 1][n] = val.y;
                Bs[kv + 2][n] = val.z;
                Bs[kv + 3][n] = val.w;
            }
        }
        __syncthreads();

        // ---- compute ----
#pragma unroll
        for (int k = 0; k < BK; k++) {
            float a[TM], b[TN];
            *reinterpret_cast<float4*>(&a[0]) =
                *reinterpret_cast<const float4*>(&As[k][ty * TM + 0]);
            *reinterpret_cast<float4*>(&a[4]) =
                *reinterpret_cast<const float4*>(&As[k][ty * TM + 4]);
            *reinterpret_cast<float4*>(&b[0]) =
                *reinterpret_cast<const float4*>(&Bs[k][tx * TN + 0]);
            *reinterpret_cast<float4*>(&b[4]) =
                *reinterpret_cast<const float4*>(&Bs[k][tx * TN + 4]);
#pragma unroll
            for (int i = 0; i < TM; i++)
#pragma unroll
                for (int j = 0; j < TN; j++)
                    acc[i][j] = fmaf(a[i], b[j], acc[i][j]);
        }
        __syncthreads();
    }

    // ---- epilogue ----
#pragma unroll
    for (int i = 0; i < TM; i++) {
        int m = bm + ty * TM + i;
#pragma unroll
        for (int j = 0; j < TN; j += 4) {
            int n = bn + tx * TN + j;
            float4 val = make_float4(acc[i][j], acc[i][j + 1],
                                     acc[i][j + 2], acc[i][j + 3]);
            if (BIAS) {
                val.x += bias[n + 0];
                val.y += bias[n + 1];
                val.z += bias[n + 2];
                val.w += bias[n + 3];
            }
            *reinterpret_cast<float4*>(&C[(size_t)m * N + n]) = val;
        }
    }
}

// ---------------- row softmax over S[E,E] -------------------------------------
__global__ __launch_bounds__(256)
void softmax_rows(float* __restrict__ S)
{
    __shared__ float buf[EE];
    __shared__ float red[256];
    const int row = blockIdx.x;
    const int tid = threadIdx.x;
    float* p = S + (size_t)row * EE;

    float lmax = -INFINITY;
    for (int i = tid; i < EE; i += 256) {
        float v = p[i];
        buf[i] = v;
        lmax = fmaxf(lmax, v);
    }
    red[tid] = lmax;
    __syncthreads();
#pragma unroll
    for (int s = 128; s > 0; s >>= 1) {
        if (tid < s) red[tid] = fmaxf(red[tid], red[tid + s]);
        __syncthreads();
    }
    const float m = red[0];
    __syncthreads();

    float lsum = 0.0f;
    for (int i = tid; i < EE; i += 256) {
        float e = expf(buf[i] - m);
        buf[i] = e;
        lsum += e;
    }
    red[tid] = lsum;
    __syncthreads();
#pragma unroll
    for (int s = 128; s > 0; s >>= 1) {
        if (tid < s) red[tid] += red[tid + s];
        __syncthreads();
    }
    const float inv = 1.0f / red[0];
    for (int i = tid; i < EE; i += 256)
        p[i] = buf[i] * inv;
}

// ---------------- launch ------------------------------------------------------
extern "C" void kernel_launch(void* const* d_in, const int* in_sizes, int n_in,
                              void* d_out, int out_size)
{
    const float* tokens = (const float*)d_in[0];
    const float* Wq     = (const float*)d_in[1];
    const float* bq     = (const float*)d_in[2];
    const float* Wk     = (const float*)d_in[3];
    const float* bk     = (const float*)d_in[4];
    const float* Wv     = (const float*)d_in[5];
    const float* bv     = (const float*)d_in[6];
    const float* Wp     = (const float*)d_in[7];
    const float* bp     = (const float*)d_in[8];
    float* out = (float*)d_out;

    float *q, *k, *v, *S, *o;
    cudaGetSymbolAddress((void**)&q, g_q);
    cudaGetSymbolAddress((void**)&k, g_k);
    cudaGetSymbolAddress((void**)&v, g_v);
    cudaGetSymbolAddress((void**)&S, g_S);
    cudaGetSymbolAddress((void**)&o, g_o);

    const dim3 blk(256);

    // QKV: [T,E] = tokens[T,E] @ W[E,E] + b
    {
        dim3 grid(EE / BN, TT / BM);
        gemm_kernel<false, false, true><<<grid, blk>>>(tokens, Wq, bq, q, TT, EE, EE);
        gemm_kernel<false, false, true><<<grid, blk>>>(tokens, Wk, bk, k, TT, EE, EE);
        gemm_kernel<false, false, true><<<grid, blk>>>(tokens, Wv, bv, v, TT, EE, EE);
    }
    // S[E,E] = q^T @ k   (K = T)
    {
        dim3 grid(EE / BN, EE / BM);
        gemm_kernel<true, false, false><<<grid, blk>>>(q, k, nullptr, S, EE, EE, TT);
    }
    // softmax rows of S
    softmax_rows<<<EE, blk>>>(S);
    // o[E,T] = S[E,E] @ v^T   (v stored [T,E] -> TB)
    {
        dim3 grid(TT / BN, EE / BM);
        gemm_kernel<false, true, false><<<grid, blk>>>(S, v, nullptr, o, EE, TT, EE);
    }
    // out[E,T] = o[E,T] @ Wp[T,T] + bp
    {
        dim3 grid(TT / BN, EE / BM);
        gemm_kernel<false, false, true><<<grid, blk>>>(o, Wp, bp, out, EE, TT, TT);
    }
}

// round 8
// speedup vs baseline: 2.4291x; 2.4291x over previous
#include <cuda_runtime.h>
#include <cuda_bf16.h>
#include <math.h>
#include <stdint.h>

#define TT 8192   // sequence length T
#define EE 4096   // embedding E

// ============================ scratch (768MB, reused) ========================
// A @0    (128MB): tokH/tokL        -> later WpH (128MB)
// B @128  (64MB) : per-weight hi/lo temp (Wq, then Wk, then Wv)
// C @192  (128MB): fp32 temp: q -> k -> v -> o
// D @320  (128MB): qTH/qTL          -> later sH/sL (32+32MB)
// E @448  (128MB): kTH/kTL          -> later oH/oL (64+64MB)
// F @576  (128MB): vH/vL            -> later WpL (128MB)
// G @704  (64MB) : S fp32
static constexpr size_t MB = 1ull << 20;
static constexpr size_t OFF_TOKH = 0,       OFF_TOKL = 64*MB;
static constexpr size_t OFF_WPH  = 0;                        // reuse A
static constexpr size_t OFF_WH   = 128*MB,  OFF_WL   = 160*MB;
static constexpr size_t OFF_F32  = 192*MB;                   // q/k/v/o fp32
static constexpr size_t OFF_QTH  = 320*MB,  OFF_QTL  = 384*MB;
static constexpr size_t OFF_SH   = 320*MB,  OFF_SL   = 352*MB;   // reuse D
static constexpr size_t OFF_KTH  = 448*MB,  OFF_KTL  = 512*MB;
static constexpr size_t OFF_OH   = 448*MB,  OFF_OL   = 512*MB;   // reuse E
static constexpr size_t OFF_VH   = 576*MB,  OFF_VL   = 640*MB;
static constexpr size_t OFF_WPL  = 576*MB;                   // reuse F
static constexpr size_t OFF_S    = 704*MB;
static constexpr size_t TOTAL_SCRATCH = 768*MB;
__device__ __align__(1024) unsigned char g_scratch[TOTAL_SCRATCH];

// ============================ PTX helpers ===================================
__device__ __forceinline__ uint32_t smem_u32(const void* p) {
    uint32_t a;
    asm("{ .reg .u64 t; cvta.to.shared.u64 t, %1; cvt.u32.u64 %0, t; }" : "=r"(a) : "l"(p));
    return a;
}
__device__ __forceinline__ void cp16(uint32_t s, const void* g) {
    asm volatile("cp.async.cg.shared.global [%0], [%1], 16;" :: "r"(s), "l"(g));
}
__device__ __forceinline__ void ldm_x4(uint32_t* r, uint32_t addr) {
    asm volatile("ldmatrix.sync.aligned.m8n8.x4.shared.b16 {%0,%1,%2,%3}, [%4];"
                 : "=r"(r[0]), "=r"(r[1]), "=r"(r[2]), "=r"(r[3]) : "r"(addr));
}
__device__ __forceinline__ void mma16816(float* c, const uint32_t* a, const uint32_t* b) {
    asm volatile(
        "mma.sync.aligned.m16n8k16.row.col.f32.bf16.bf16.f32 "
        "{%0,%1,%2,%3}, {%4,%5,%6,%7}, {%8,%9}, {%0,%1,%2,%3};"
        : "+f"(c[0]), "+f"(c[1]), "+f"(c[2]), "+f"(c[3])
        : "r"(a[0]), "r"(a[1]), "r"(a[2]), "r"(a[3]), "r"(b[0]), "r"(b[1]));
}

// ============================ bf16-split GEMM (mma.sync) =====================
// C[M,N] = sum_k A[m,k]*B[n,k]; A,B given as bf16 hi/lo pairs, K-major rows.
// Block 128x128x32, 256 threads, warp tile 64x32, 3-term split accumulation.
constexpr int BK = 32;
constexpr int STAGES = 3;
constexpr int LROW = 40;                          // smem row stride in ushorts (80B)
constexpr int ARR_BYTES = 128 * LROW * 2;         // 10240 per operand tile
constexpr int STG_BYTES = 4 * ARR_BYTES;          // Ahi,Alo,Bhi,Blo
constexpr int SMEM_BYTES = STAGES * STG_BYTES;    // 122880

template <bool BIAS>
__global__ __launch_bounds__(256, 1)
void hm_gemm(const unsigned short* __restrict__ Ah, const unsigned short* __restrict__ Al,
             const unsigned short* __restrict__ Bh, const unsigned short* __restrict__ Bl,
             const float* __restrict__ bias, float* __restrict__ C,
             int Ntot, int Ktot)
{
    extern __shared__ __align__(128) char smem[];
    const uint32_t sb = smem_u32(smem);
    const int tid = threadIdx.x, lane = tid & 31, wid = tid >> 5;
    const int bm = blockIdx.y * 128, bn = blockIdx.x * 128;
    const int wm = (wid >> 2) * 64, wn = (wid & 3) * 32;
    const int nch = Ktot >> 5;

    // cp.async mapping: 2 chunks of 16B per operand array per thread
    const int r0 = tid >> 2;            // 0..63
    const int lc = (tid & 3) * 8;       // ushort offset within row (16B granularity)

    auto load_stage = [&](int stg, int ch) {
        const uint32_t st = sb + stg * STG_BYTES;
        const size_t ko = (size_t)(ch * BK) + lc;
        cp16(st + 0 * ARR_BYTES + (r0)      * 80 + lc * 2, Ah + (size_t)(bm + r0)      * Ktot + ko);
        cp16(st + 0 * ARR_BYTES + (r0 + 64) * 80 + lc * 2, Ah + (size_t)(bm + r0 + 64) * Ktot + ko);
        cp16(st + 1 * ARR_BYTES + (r0)      * 80 + lc * 2, Al + (size_t)(bm + r0)      * Ktot + ko);
        cp16(st + 1 * ARR_BYTES + (r0 + 64) * 80 + lc * 2, Al + (size_t)(bm + r0 + 64) * Ktot + ko);
        cp16(st + 2 * ARR_BYTES + (r0)      * 80 + lc * 2, Bh + (size_t)(bn + r0)      * Ktot + ko);
        cp16(st + 2 * ARR_BYTES + (r0 + 64) * 80 + lc * 2, Bh + (size_t)(bn + r0 + 64) * Ktot + ko);
        cp16(st + 3 * ARR_BYTES + (r0)      * 80 + lc * 2, Bl + (size_t)(bn + r0)      * Ktot + ko);
        cp16(st + 3 * ARR_BYTES + (r0 + 64) * 80 + lc * 2, Bl + (size_t)(bn + r0 + 64) * Ktot + ko);
        asm volatile("cp.async.commit_group;");
    };

    // ldmatrix lane-address components
    const int sel = lane >> 3, r8 = lane & 7;
    // A: mats (m0-7,k0-7),(m8-15,k0-7),(m0-7,k8-15),(m8-15,k8-15)
    const uint32_t aoffA = (uint32_t)((wm + (sel & 1) * 8 + r8) * 80 + (sel >> 1) * 16);
    // B stored [N,K] = B^T row-major -> NON-trans ldmatrix gives col-major B frags.
    // mats (n0-7,k0-7),(n0-7,k8-15),(n8-15,k0-7),(n8-15,k8-15)
    const uint32_t aoffB = (uint32_t)((wn + (sel >> 1) * 8 + r8) * 80 + (sel & 1) * 16);

    float acc[4][4][4];
#pragma unroll
    for (int a = 0; a < 4; a++)
#pragma unroll
        for (int b = 0; b < 4; b++)
#pragma unroll
            for (int c = 0; c < 4; c++) acc[a][b][c] = 0.0f;

    load_stage(0, 0);
    load_stage(1, 1);

    for (int i = 0; i < nch; i++) {
        asm volatile("cp.async.wait_group 1;");
        __syncthreads();
        if (i + STAGES - 1 < nch) load_stage((i + STAGES - 1) % STAGES, i + STAGES - 1);

        const uint32_t st = sb + (i % STAGES) * STG_BYTES;
#pragma unroll
        for (int k16 = 0; k16 < 2; k16++) {
            const uint32_t ko = k16 * 32;  // 16 ushorts = 32B
            uint32_t ah[4][4], al[4][4], bh[4][2], bl[4][2];
#pragma unroll
            for (int mt = 0; mt < 4; mt++) {
                ldm_x4(ah[mt], st + 0 * ARR_BYTES + aoffA + mt * 1280 + ko);
                ldm_x4(al[mt], st + 1 * ARR_BYTES + aoffA + mt * 1280 + ko);
            }
#pragma unroll
            for (int p = 0; p < 2; p++) {
                uint32_t t[4];
                ldm_x4(t, st + 2 * ARR_BYTES + aoffB + p * 1280 + ko);   // non-trans
                bh[2 * p][0] = t[0]; bh[2 * p][1] = t[1];
                bh[2 * p + 1][0] = t[2]; bh[2 * p + 1][1] = t[3];
                ldm_x4(t, st + 3 * ARR_BYTES + aoffB + p * 1280 + ko);   // non-trans
                bl[2 * p][0] = t[0]; bl[2 * p][1] = t[1];
                bl[2 * p + 1][0] = t[2]; bl[2 * p + 1][1] = t[3];
            }
#pragma unroll
            for (int mt = 0; mt < 4; mt++)
#pragma unroll
                for (int nt = 0; nt < 4; nt++) {
                    mma16816(acc[mt][nt], ah[mt], bh[nt]);  // hi*hi
                    mma16816(acc[mt][nt], ah[mt], bl[nt]);  // hi*lo
                    mma16816(acc[mt][nt], al[mt], bh[nt]);  // lo*hi
                }
        }
        __syncthreads();
    }

    // ---- epilogue ----
    const int g = lane >> 2, tg = lane & 3;
#pragma unroll
    for (int mt = 0; mt < 4; mt++) {
#pragma unroll
        for (int nt = 0; nt < 4; nt++) {
            const int m = bm + wm + mt * 16 + g;
            const int n = bn + wn + nt * 8 + tg * 2;
            float bx = 0.f, by = 0.f;
            if (BIAS) { bx = bias[n]; by = bias[n + 1]; }
            float2 v0 = make_float2(acc[mt][nt][0] + bx, acc[mt][nt][1] + by);
            float2 v1 = make_float2(acc[mt][nt][2] + bx, acc[mt][nt][3] + by);
            *reinterpret_cast<float2*>(&C[(size_t)m * Ntot + n]) = v0;
            *reinterpret_cast<float2*>(&C[(size_t)(m + 8) * Ntot + n]) = v1;
        }
    }
}

// ============================ split kernels =================================
__device__ __forceinline__ void split1(float x, unsigned short& h, unsigned short& l) {
    __nv_bfloat16 hb = __float2bfloat16_rn(x);
    float r = x - __bfloat162float(hb);
    __nv_bfloat16 lb = __float2bfloat16_rn(r);
    h = __bfloat16_as_ushort(hb);
    l = __bfloat16_as_ushort(lb);
}

__global__ __launch_bounds__(256)
void split_dir(const float4* __restrict__ x, ushort4* __restrict__ hi,
               ushort4* __restrict__ lo, size_t n4)
{
    size_t i = (size_t)blockIdx.x * blockDim.x + threadIdx.x;
    if (i >= n4) return;
    float4 v = x[i];
    ushort4 h, l;
    split1(v.x, h.x, l.x);
    split1(v.y, h.y, l.y);
    split1(v.z, h.z, l.z);
    split1(v.w, h.w, l.w);
    hi[i] = h;
    lo[i] = l;
}

// X [R,C] fp32 -> hi/lo [C,R] bf16
__global__ __launch_bounds__(256)
void split_tr(const float* __restrict__ x, unsigned short* __restrict__ hi,
              unsigned short* __restrict__ lo, int R, int C)
{
    __shared__ float t[32][33];
    const int c0 = blockIdx.x * 32, r0 = blockIdx.y * 32;
    const int tx = threadIdx.x, ty = threadIdx.y;  // 32 x 8
#pragma unroll
    for (int j = 0; j < 32; j += 8)
        t[ty + j][tx] = x[(size_t)(r0 + ty + j) * C + c0 + tx];
    __syncthreads();
#pragma unroll
    for (int j = 0; j < 32; j += 8) {
        float v = t[tx][ty + j];
        unsigned short h, l;
        split1(v, h, l);
        size_t o = (size_t)(c0 + ty + j) * R + r0 + tx;
        hi[o] = h;
        lo[o] = l;
    }
}

// ============================ softmax =======================================
__global__ __launch_bounds__(256)
void softmax_rows(float* __restrict__ S)
{
    __shared__ float buf[EE];
    __shared__ float red[256];
    const int row = blockIdx.x;
    const int tid = threadIdx.x;
    float* p = S + (size_t)row * EE;

    float lmax = -INFINITY;
    for (int i = tid; i < EE; i += 256) {
        float v = p[i];
        buf[i] = v;
        lmax = fmaxf(lmax, v);
    }
    red[tid] = lmax;
    __syncthreads();
#pragma unroll
    for (int s = 128; s > 0; s >>= 1) {
        if (tid < s) red[tid] = fmaxf(red[tid], red[tid + s]);
        __syncthreads();
    }
    const float m = red[0];
    __syncthreads();
    float lsum = 0.0f;
    for (int i = tid; i < EE; i += 256) {
        float e = expf(buf[i] - m);
        buf[i] = e;
        lsum += e;
    }
    red[tid] = lsum;
    __syncthreads();
#pragma unroll
    for (int s = 128; s > 0; s >>= 1) {
        if (tid < s) red[tid] += red[tid + s];
        __syncthreads();
    }
    const float inv = 1.0f / red[0];
    for (int i = tid; i < EE; i += 256)
        p[i] = buf[i] * inv;
}

// ============================ host side =====================================
extern "C" void kernel_launch(void* const* d_in, const int* in_sizes, int n_in,
                              void* d_out, int out_size)
{
    const float* tokens = (const float*)d_in[0];
    const float* Wq = (const float*)d_in[1];
    const float* bq = (const float*)d_in[2];
    const float* Wk = (const float*)d_in[3];
    const float* bk = (const float*)d_in[4];
    const float* Wv = (const float*)d_in[5];
    const float* bv = (const float*)d_in[6];
    const float* Wp = (const float*)d_in[7];
    const float* bp = (const float*)d_in[8];
    float* out = (float*)d_out;

    unsigned char* base;
    cudaGetSymbolAddress((void**)&base, g_scratch);
    float* f32tmp = (float*)(base + OFF_F32);   // q -> k -> v -> o
    float* S      = (float*)(base + OFF_S);
#define PU(off) ((unsigned short*)(base + (off)))

    // idempotent, non-allocating, non-syncing: safe on every call (incl. capture)
    cudaFuncSetAttribute(hm_gemm<true>,  cudaFuncAttributeMaxDynamicSharedMemorySize, SMEM_BYTES);
    cudaFuncSetAttribute(hm_gemm<false>, cudaFuncAttributeMaxDynamicSharedMemorySize, SMEM_BYTES);

    const dim3 blk(256);
    const dim3 tb(32, 8);
    const dim3 gQKV(EE / 128, TT / 128);   // [T,E] outputs
    const dim3 gS(EE / 128, EE / 128);     // [E,E]
    const dim3 gO(TT / 128, EE / 128);     // [E,T]
    const size_t nTE4 = (size_t)TT * EE / 4;
    const unsigned bTE = (unsigned)((nTE4 + 255) / 256);

    // 1. split tokens -> A
    split_dir<<<bTE, 256>>>((const float4*)tokens, (ushort4*)PU(OFF_TOKH),
                            (ushort4*)PU(OFF_TOKL), nTE4);

    // 2. q = tok @ Wq + bq ; transpose-split q -> D
    split_tr<<<dim3(EE / 32, EE / 32), tb>>>(Wq, PU(OFF_WH), PU(OFF_WL), EE, EE);
    hm_gemm<true><<<gQKV, blk, SMEM_BYTES>>>(PU(OFF_TOKH), PU(OFF_TOKL),
                                             PU(OFF_WH), PU(OFF_WL), bq, f32tmp, EE, EE);
    split_tr<<<dim3(EE / 32, TT / 32), tb>>>(f32tmp, PU(OFF_QTH), PU(OFF_QTL), TT, EE);

    // 3. k = tok @ Wk + bk ; transpose-split k -> E
    split_tr<<<dim3(EE / 32, EE / 32), tb>>>(Wk, PU(OFF_WH), PU(OFF_WL), EE, EE);
    hm_gemm<true><<<gQKV, blk, SMEM_BYTES>>>(PU(OFF_TOKH), PU(OFF_TOKL),
                                             PU(OFF_WH), PU(OFF_WL), bk, f32tmp, EE, EE);
    split_tr<<<dim3(EE / 32, TT / 32), tb>>>(f32tmp, PU(OFF_KTH), PU(OFF_KTL), TT, EE);

    // 4. v = tok @ Wv + bv ; split v -> F
    split_tr<<<dim3(EE / 32, EE / 32), tb>>>(Wv, PU(OFF_WH), PU(OFF_WL), EE, EE);
    hm_gemm<true><<<gQKV, blk, SMEM_BYTES>>>(PU(OFF_TOKH), PU(OFF_TOKL),
                                             PU(OFF_WH), PU(OFF_WL), bv, f32tmp, EE, EE);
    split_dir<<<bTE, 256>>>((const float4*)f32tmp, (ushort4*)PU(OFF_VH),
                            (ushort4*)PU(OFF_VL), nTE4);

    // 5. S = q^T @ k : [E,E], K=T ; softmax ; split S -> D (reuse)
    hm_gemm<false><<<gS, blk, SMEM_BYTES>>>(PU(OFF_QTH), PU(OFF_QTL),
                                            PU(OFF_KTH), PU(OFF_KTL), nullptr, S, EE, TT);
    softmax_rows<<<EE, 256>>>(S);
    {
        size_t n4 = (size_t)EE * EE / 4;
        split_dir<<<(unsigned)((n4 + 255) / 256), 256>>>(
            (const float4*)S, (ushort4*)PU(OFF_SH), (ushort4*)PU(OFF_SL), n4);
    }

    // 6. o = S @ v^T : [E,T], K=E ; split o -> E (reuse)
    hm_gemm<false><<<gO, blk, SMEM_BYTES>>>(PU(OFF_SH), PU(OFF_SL),
                                            PU(OFF_VH), PU(OFF_VL), nullptr, f32tmp, TT, EE);
    split_dir<<<bTE, 256>>>((const float4*)f32tmp, (ushort4*)PU(OFF_OH),
                            (ushort4*)PU(OFF_OL), nTE4);

    // 7. split Wp -> A/F (reuse; tok & v splits dead) ; out = o @ Wp + bp
    split_tr<<<dim3(TT / 32, TT / 32), tb>>>(Wp, PU(OFF_WPH), PU(OFF_WPL), TT, TT);
    hm_gemm<true><<<gO, blk, SMEM_BYTES>>>(PU(OFF_OH), PU(OFF_OL),
                                           PU(OFF_WPH), PU(OFF_WPL), bp, out, TT, TT);
#undef PU
}

// round 9
// speedup vs baseline: 2.8202x; 1.1610x over previous
#include <cuda_runtime.h>
#include <cuda_bf16.h>
#include <math.h>
#include <stdint.h>

#define TT 8192   // sequence length T
#define EE 4096   // embedding E

// ============================ scratch (768MB, reused) ========================
static constexpr size_t MB = 1ull << 20;
static constexpr size_t OFF_TOKH = 0,       OFF_TOKL = 64*MB;
static constexpr size_t OFF_WPH  = 0;                        // reuse A
static constexpr size_t OFF_WH   = 128*MB,  OFF_WL   = 160*MB;
static constexpr size_t OFF_F32  = 192*MB;                   // q/k fp32 temp
static constexpr size_t OFF_QTH  = 320*MB,  OFF_QTL  = 384*MB;
static constexpr size_t OFF_SH   = 320*MB,  OFF_SL   = 352*MB;   // reuse D
static constexpr size_t OFF_KTH  = 448*MB,  OFF_KTL  = 512*MB;
static constexpr size_t OFF_OH   = 448*MB,  OFF_OL   = 512*MB;   // reuse E
static constexpr size_t OFF_VH   = 576*MB,  OFF_VL   = 640*MB;
static constexpr size_t OFF_WPL  = 576*MB;                   // reuse F
static constexpr size_t OFF_S    = 704*MB;
static constexpr size_t TOTAL_SCRATCH = 768*MB;
__device__ __align__(1024) unsigned char g_scratch[TOTAL_SCRATCH];

// ============================ PTX helpers ===================================
__device__ __forceinline__ uint32_t smem_u32(const void* p) {
    uint32_t a;
    asm("{ .reg .u64 t; cvta.to.shared.u64 t, %1; cvt.u32.u64 %0, t; }" : "=r"(a) : "l"(p));
    return a;
}
__device__ __forceinline__ void cp16(uint32_t s, const void* g) {
    asm volatile("cp.async.cg.shared.global [%0], [%1], 16;" :: "r"(s), "l"(g));
}
__device__ __forceinline__ void ldm_x4(uint32_t* r, uint32_t addr) {
    asm volatile("ldmatrix.sync.aligned.m8n8.x4.shared.b16 {%0,%1,%2,%3}, [%4];"
                 : "=r"(r[0]), "=r"(r[1]), "=r"(r[2]), "=r"(r[3]) : "r"(addr));
}
__device__ __forceinline__ void mma16816(float* c, const uint32_t* a, const uint32_t* b) {
    asm volatile(
        "mma.sync.aligned.m16n8k16.row.col.f32.bf16.bf16.f32 "
        "{%0,%1,%2,%3}, {%4,%5,%6,%7}, {%8,%9}, {%0,%1,%2,%3};"
        : "+f"(c[0]), "+f"(c[1]), "+f"(c[2]), "+f"(c[3])
        : "r"(a[0]), "r"(a[1]), "r"(a[2]), "r"(a[3]), "r"(b[0]), "r"(b[1]));
}

__device__ __forceinline__ void split1(float x, unsigned short& h, unsigned short& l) {
    __nv_bfloat16 hb = __float2bfloat16_rn(x);
    float r = x - __bfloat162float(hb);
    __nv_bfloat16 lb = __float2bfloat16_rn(r);
    h = __bfloat16_as_ushort(hb);
    l = __bfloat16_as_ushort(lb);
}

// ============================ bf16-split GEMM (mma.sync) =====================
// C[M,N] = sum_k A[m,k]*B[n,k]; A,B bf16 hi/lo pairs, K-major rows.
// Block 128x128x32, 256 threads, warp tile 64x32. 2-stage cp.async pipeline,
// 2 CTAs/SM. Register-lean: al reuses ah fragment registers.
// OUT: 0 = fp32 C,  1 = hi/lo bf16 split outputs.
constexpr int BK = 32;
constexpr int LROW80 = 80;                        // smem row stride bytes
constexpr int ARR_BYTES = 128 * LROW80;           // 10240 per operand tile
constexpr int STG_BYTES = 4 * ARR_BYTES;          // Ahi,Alo,Bhi,Blo = 40960
constexpr int SMEM_BYTES = 2 * STG_BYTES;         // 81920 (2 stages)

template <bool BIAS, int OUT>
__global__ __launch_bounds__(256, 2)
void hm_gemm(const unsigned short* __restrict__ Ah, const unsigned short* __restrict__ Al,
             const unsigned short* __restrict__ Bh, const unsigned short* __restrict__ Bl,
             const float* __restrict__ bias, float* __restrict__ C,
             unsigned short* __restrict__ Chi, unsigned short* __restrict__ Clo,
             int Ntot, int Ktot)
{
    extern __shared__ __align__(128) char smem[];
    const uint32_t sb = smem_u32(smem);
    const int tid = threadIdx.x, lane = tid & 31, wid = tid >> 5;
    const int bm = blockIdx.y * 128, bn = blockIdx.x * 128;
    const int wm = (wid >> 2) * 64, wn = (wid & 3) * 32;
    const int nch = Ktot >> 5;

    const int r0 = tid >> 2;            // 0..63
    const int lc = (tid & 3) * 8;       // ushort offset within row

    auto load_stage = [&](int stg, int ch) {
        const uint32_t st = sb + stg * STG_BYTES;
        const size_t ko = (size_t)(ch * BK) + lc;
        cp16(st + 0 * ARR_BYTES + (r0)      * 80 + lc * 2, Ah + (size_t)(bm + r0)      * Ktot + ko);
        cp16(st + 0 * ARR_BYTES + (r0 + 64) * 80 + lc * 2, Ah + (size_t)(bm + r0 + 64) * Ktot + ko);
        cp16(st + 1 * ARR_BYTES + (r0)      * 80 + lc * 2, Al + (size_t)(bm + r0)      * Ktot + ko);
        cp16(st + 1 * ARR_BYTES + (r0 + 64) * 80 + lc * 2, Al + (size_t)(bm + r0 + 64) * Ktot + ko);
        cp16(st + 2 * ARR_BYTES + (r0)      * 80 + lc * 2, Bh + (size_t)(bn + r0)      * Ktot + ko);
        cp16(st + 2 * ARR_BYTES + (r0 + 64) * 80 + lc * 2, Bh + (size_t)(bn + r0 + 64) * Ktot + ko);
        cp16(st + 3 * ARR_BYTES + (r0)      * 80 + lc * 2, Bl + (size_t)(bn + r0)      * Ktot + ko);
        cp16(st + 3 * ARR_BYTES + (r0 + 64) * 80 + lc * 2, Bl + (size_t)(bn + r0 + 64) * Ktot + ko);
        asm volatile("cp.async.commit_group;");
    };

    // ldmatrix lane-address components
    const int sel = lane >> 3, r8 = lane & 7;
    // A quadrants: (m0-7,k0-7),(m8-15,k0-7),(m0-7,k8-15),(m8-15,k8-15)
    const uint32_t aoffA = (uint32_t)((wm + (sel & 1) * 8 + r8) * 80 + (sel >> 1) * 16);
    // B (stored [N,K]): quadrants (n0-7,k0-7),(n0-7,k8-15),(n8-15,k0-7),(n8-15,k8-15)
    const uint32_t aoffB = (uint32_t)((wn + (sel >> 1) * 8 + r8) * 80 + (sel & 1) * 16);

    float acc[4][4][4];
#pragma unroll
    for (int a = 0; a < 4; a++)
#pragma unroll
        for (int b = 0; b < 4; b++)
#pragma unroll
            for (int c = 0; c < 4; c++) acc[a][b][c] = 0.0f;

    load_stage(0, 0);
    if (nch > 1) load_stage(1, 1);

    for (int i = 0; i < nch; i++) {
        asm volatile("cp.async.wait_group 1;");
        __syncthreads();

        const uint32_t st = sb + (i & 1) * STG_BYTES;
#pragma unroll
        for (int k16 = 0; k16 < 2; k16++) {
            const uint32_t ko = k16 * 32;  // 16 ushorts = 32B
            uint32_t af[4][4], bh[4][2], bl[4][2];
            // --- hi A frags + B frags ---
#pragma unroll
            for (int mt = 0; mt < 4; mt++)
                ldm_x4(af[mt], st + 0 * ARR_BYTES + aoffA + mt * 1280 + ko);
#pragma unroll
            for (int p = 0; p < 2; p++) {
                uint32_t t[4];
                ldm_x4(t, st + 2 * ARR_BYTES + aoffB + p * 1280 + ko);
                bh[2 * p][0] = t[0]; bh[2 * p][1] = t[1];
                bh[2 * p + 1][0] = t[2]; bh[2 * p + 1][1] = t[3];
                ldm_x4(t, st + 3 * ARR_BYTES + aoffB + p * 1280 + ko);
                bl[2 * p][0] = t[0]; bl[2 * p][1] = t[1];
                bl[2 * p + 1][0] = t[2]; bl[2 * p + 1][1] = t[3];
            }
#pragma unroll
            for (int mt = 0; mt < 4; mt++)
#pragma unroll
                for (int nt = 0; nt < 4; nt++) {
                    mma16816(acc[mt][nt], af[mt], bh[nt]);  // hi*hi
                    mma16816(acc[mt][nt], af[mt], bl[nt]);  // hi*lo
                }
            // --- lo A frags reuse af registers ---
#pragma unroll
            for (int mt = 0; mt < 4; mt++)
                ldm_x4(af[mt], st + 1 * ARR_BYTES + aoffA + mt * 1280 + ko);
#pragma unroll
            for (int mt = 0; mt < 4; mt++)
#pragma unroll
                for (int nt = 0; nt < 4; nt++)
                    mma16816(acc[mt][nt], af[mt], bh[nt]);  // lo*hi
        }
        __syncthreads();
        if (i + 2 < nch) load_stage(i & 1, i + 2);
    }

    // ---- epilogue ----
    const int g = lane >> 2, tg = lane & 3;
#pragma unroll
    for (int mt = 0; mt < 4; mt++) {
#pragma unroll
        for (int nt = 0; nt < 4; nt++) {
            const int m = bm + wm + mt * 16 + g;
            const int n = bn + wn + nt * 8 + tg * 2;
            float bx = 0.f, by = 0.f;
            if (BIAS) { bx = bias[n]; by = bias[n + 1]; }
            float v00 = acc[mt][nt][0] + bx, v01 = acc[mt][nt][1] + by;
            float v10 = acc[mt][nt][2] + bx, v11 = acc[mt][nt][3] + by;
            if (OUT == 0) {
                *reinterpret_cast<float2*>(&C[(size_t)m * Ntot + n]) = make_float2(v00, v01);
                *reinterpret_cast<float2*>(&C[(size_t)(m + 8) * Ntot + n]) = make_float2(v10, v11);
            } else {
                ushort2 h0, l0, h1, l1;
                split1(v00, h0.x, l0.x); split1(v01, h0.y, l0.y);
                split1(v10, h1.x, l1.x); split1(v11, h1.y, l1.y);
                *reinterpret_cast<ushort2*>(&Chi[(size_t)m * Ntot + n]) = h0;
                *reinterpret_cast<ushort2*>(&Clo[(size_t)m * Ntot + n]) = l0;
                *reinterpret_cast<ushort2*>(&Chi[(size_t)(m + 8) * Ntot + n]) = h1;
                *reinterpret_cast<ushort2*>(&Clo[(size_t)(m + 8) * Ntot + n]) = l1;
            }
        }
    }
}

// ============================ split kernels =================================
__global__ __launch_bounds__(256)
void split_dir(const float4* __restrict__ x, ushort4* __restrict__ hi,
               ushort4* __restrict__ lo, size_t n4)
{
    size_t i = (size_t)blockIdx.x * blockDim.x + threadIdx.x;
    if (i >= n4) return;
    float4 v = x[i];
    ushort4 h, l;
    split1(v.x, h.x, l.x);
    split1(v.y, h.y, l.y);
    split1(v.z, h.z, l.z);
    split1(v.w, h.w, l.w);
    hi[i] = h;
    lo[i] = l;
}

// X [R,C] fp32 -> hi/lo [C,R] bf16
__global__ __launch_bounds__(256)
void split_tr(const float* __restrict__ x, unsigned short* __restrict__ hi,
              unsigned short* __restrict__ lo, int R, int C)
{
    __shared__ float t[32][33];
    const int c0 = blockIdx.x * 32, r0 = blockIdx.y * 32;
    const int tx = threadIdx.x, ty = threadIdx.y;  // 32 x 8
#pragma unroll
    for (int j = 0; j < 32; j += 8)
        t[ty + j][tx] = x[(size_t)(r0 + ty + j) * C + c0 + tx];
    __syncthreads();
#pragma unroll
    for (int j = 0; j < 32; j += 8) {
        float v = t[tx][ty + j];
        unsigned short h, l;
        split1(v, h, l);
        size_t o = (size_t)(c0 + ty + j) * R + r0 + tx;
        hi[o] = h;
        lo[o] = l;
    }
}

// ============================ softmax =======================================
__global__ __launch_bounds__(256)
void softmax_rows(float* __restrict__ S)
{
    __shared__ float buf[EE];
    __shared__ float red[256];
    const int row = blockIdx.x;
    const int tid = threadIdx.x;
    float* p = S + (size_t)row * EE;

    float lmax = -INFINITY;
    for (int i = tid; i < EE; i += 256) {
        float v = p[i];
        buf[i] = v;
        lmax = fmaxf(lmax, v);
    }
    red[tid] = lmax;
    __syncthreads();
#pragma unroll
    for (int s = 128; s > 0; s >>= 1) {
        if (tid < s) red[tid] = fmaxf(red[tid], red[tid + s]);
        __syncthreads();
    }
    const float m = red[0];
    __syncthreads();
    float lsum = 0.0f;
    for (int i = tid; i < EE; i += 256) {
        float e = expf(buf[i] - m);
        buf[i] = e;
        lsum += e;
    }
    red[tid] = lsum;
    __syncthreads();
#pragma unroll
    for (int s = 128; s > 0; s >>= 1) {
        if (tid < s) red[tid] += red[tid + s];
        __syncthreads();
    }
    const float inv = 1.0f / red[0];
    for (int i = tid; i < EE; i += 256)
        p[i] = buf[i] * inv;
}

// ============================ host side =====================================
extern "C" void kernel_launch(void* const* d_in, const int* in_sizes, int n_in,
                              void* d_out, int out_size)
{
    const float* tokens = (const float*)d_in[0];
    const float* Wq = (const float*)d_in[1];
    const float* bq = (const float*)d_in[2];
    const float* Wk = (const float*)d_in[3];
    const float* bk = (const float*)d_in[4];
    const float* Wv = (const float*)d_in[5];
    const float* bv = (const float*)d_in[6];
    const float* Wp = (const float*)d_in[7];
    const float* bp = (const float*)d_in[8];
    float* out = (float*)d_out;

    unsigned char* base;
    cudaGetSymbolAddress((void**)&base, g_scratch);
    float* f32tmp = (float*)(base + OFF_F32);   // q -> k fp32
    float* S      = (float*)(base + OFF_S);
#define PU(off) ((unsigned short*)(base + (off)))

    cudaFuncSetAttribute(hm_gemm<true, 0>,  cudaFuncAttributeMaxDynamicSharedMemorySize, SMEM_BYTES);
    cudaFuncSetAttribute(hm_gemm<true, 1>,  cudaFuncAttributeMaxDynamicSharedMemorySize, SMEM_BYTES);
    cudaFuncSetAttribute(hm_gemm<false, 0>, cudaFuncAttributeMaxDynamicSharedMemorySize, SMEM_BYTES);
    cudaFuncSetAttribute(hm_gemm<false, 1>, cudaFuncAttributeMaxDynamicSharedMemorySize, SMEM_BYTES);

    const dim3 blk(256);
    const dim3 tb(32, 8);
    const dim3 gQKV(EE / 128, TT / 128);   // [T,E] outputs
    const dim3 gS(EE / 128, EE / 128);     // [E,E]
    const dim3 gO(TT / 128, EE / 128);     // [E,T]
    const size_t nTE4 = (size_t)TT * EE / 4;
    const unsigned bTE = (unsigned)((nTE4 + 255) / 256);

    // 1. split tokens
    split_dir<<<bTE, 256>>>((const float4*)tokens, (ushort4*)PU(OFF_TOKH),
                            (ushort4*)PU(OFF_TOKL), nTE4);

    // 2. q = tok @ Wq + bq (fp32) ; transpose-split q
    split_tr<<<dim3(EE / 32, EE / 32), tb>>>(Wq, PU(OFF_WH), PU(OFF_WL), EE, EE);
    hm_gemm<true, 0><<<gQKV, blk, SMEM_BYTES>>>(PU(OFF_TOKH), PU(OFF_TOKL),
        PU(OFF_WH), PU(OFF_WL), bq, f32tmp, nullptr, nullptr, EE, EE);
    split_tr<<<dim3(EE / 32, TT / 32), tb>>>(f32tmp, PU(OFF_QTH), PU(OFF_QTL), TT, EE);

    // 3. k = tok @ Wk + bk (fp32) ; transpose-split k
    split_tr<<<dim3(EE / 32, EE / 32), tb>>>(Wk, PU(OFF_WH), PU(OFF_WL), EE, EE);
    hm_gemm<true, 0><<<gQKV, blk, SMEM_BYTES>>>(PU(OFF_TOKH), PU(OFF_TOKL),
        PU(OFF_WH), PU(OFF_WL), bk, f32tmp, nullptr, nullptr, EE, EE);
    split_tr<<<dim3(EE / 32, TT / 32), tb>>>(f32tmp, PU(OFF_KTH), PU(OFF_KTL), TT, EE);

    // 4. v = tok @ Wv + bv -> fused split epilogue
    split_tr<<<dim3(EE / 32, EE / 32), tb>>>(Wv, PU(OFF_WH), PU(OFF_WL), EE, EE);
    hm_gemm<true, 1><<<gQKV, blk, SMEM_BYTES>>>(PU(OFF_TOKH), PU(OFF_TOKL),
        PU(OFF_WH), PU(OFF_WL), bv, nullptr, PU(OFF_VH), PU(OFF_VL), EE, EE);

    // 5. S = q^T @ k : [E,E], K=T ; softmax ; split S
    hm_gemm<false, 0><<<gS, blk, SMEM_BYTES>>>(PU(OFF_QTH), PU(OFF_QTL),
        PU(OFF_KTH), PU(OFF_KTL), nullptr, S, nullptr, nullptr, EE, TT);
    softmax_rows<<<EE, 256>>>(S);
    {
        size_t n4 = (size_t)EE * EE / 4;
        split_dir<<<(unsigned)((n4 + 255) / 256), 256>>>(
            (const float4*)S, (ushort4*)PU(OFF_SH), (ushort4*)PU(OFF_SL), n4);
    }

    // 6. o = S @ v^T : [E,T], K=E -> fused split epilogue
    hm_gemm<false, 1><<<gO, blk, SMEM_BYTES>>>(PU(OFF_SH), PU(OFF_SL),
        PU(OFF_VH), PU(OFF_VL), nullptr, nullptr, PU(OFF_OH), PU(OFF_OL), TT, EE);

    // 7. split Wp ; out = o @ Wp + bp (fp32 to d_out)
    split_tr<<<dim3(TT / 32, TT / 32), tb>>>(Wp, PU(OFF_WPH), PU(OFF_WPL), TT, TT);
    hm_gemm<true, 0><<<gO, blk, SMEM_BYTES>>>(PU(OFF_OH), PU(OFF_OL),
        PU(OFF_WPH), PU(OFF_WPL), bp, out, nullptr, nullptr, TT, TT);
#undef PU
}

// round 10
// speedup vs baseline: 2.9195x; 1.0352x over previous
#include <cuda_runtime.h>
#include <cuda_bf16.h>
#include <math.h>
#include <stdint.h>

#define TT 8192   // sequence length T
#define EE 4096   // embedding E

// ============================ scratch (768MB, reused) ========================
static constexpr size_t MB = 1ull << 20;
static constexpr size_t OFF_TOKH = 0,       OFF_TOKL = 64*MB;
static constexpr size_t OFF_WPH  = 0;                        // reuse A
static constexpr size_t OFF_WH   = 128*MB,  OFF_WL   = 160*MB;
static constexpr size_t OFF_F32  = 192*MB;                   // q/k fp32 temp
static constexpr size_t OFF_QTH  = 320*MB,  OFF_QTL  = 384*MB;
static constexpr size_t OFF_SH   = 320*MB,  OFF_SL   = 352*MB;   // reuse D
static constexpr size_t OFF_KTH  = 448*MB,  OFF_KTL  = 512*MB;
static constexpr size_t OFF_OH   = 448*MB,  OFF_OL   = 512*MB;   // reuse E
static constexpr size_t OFF_VH   = 576*MB,  OFF_VL   = 640*MB;
static constexpr size_t OFF_WPL  = 576*MB;                   // reuse F
static constexpr size_t OFF_S    = 704*MB;
static constexpr size_t TOTAL_SCRATCH = 768*MB;
__device__ __align__(1024) unsigned char g_scratch[TOTAL_SCRATCH];

// ============================ PTX helpers ===================================
__device__ __forceinline__ uint32_t smem_u32(const void* p) {
    uint32_t a;
    asm("{ .reg .u64 t; cvta.to.shared.u64 t, %1; cvt.u32.u64 %0, t; }" : "=r"(a) : "l"(p));
    return a;
}
__device__ __forceinline__ void cp16(uint32_t s, const void* g) {
    asm volatile("cp.async.cg.shared.global [%0], [%1], 16;" :: "r"(s), "l"(g));
}
__device__ __forceinline__ void ldm_x4(uint32_t* r, uint32_t addr) {
    asm volatile("ldmatrix.sync.aligned.m8n8.x4.shared.b16 {%0,%1,%2,%3}, [%4];"
                 : "=r"(r[0]), "=r"(r[1]), "=r"(r[2]), "=r"(r[3]) : "r"(addr));
}
__device__ __forceinline__ void mma16816(float* c, const uint32_t* a, const uint32_t* b) {
    asm volatile(
        "mma.sync.aligned.m16n8k16.row.col.f32.bf16.bf16.f32 "
        "{%0,%1,%2,%3}, {%4,%5,%6,%7}, {%8,%9}, {%0,%1,%2,%3};"
        : "+f"(c[0]), "+f"(c[1]), "+f"(c[2]), "+f"(c[3])
        : "r"(a[0]), "r"(a[1]), "r"(a[2]), "r"(a[3]), "r"(b[0]), "r"(b[1]));
}

__device__ __forceinline__ void split1(float x, unsigned short& h, unsigned short& l) {
    __nv_bfloat16 hb = __float2bfloat16_rn(x);
    float r = x - __bfloat162float(hb);
    __nv_bfloat16 lb = __float2bfloat16_rn(r);
    h = __bfloat16_as_ushort(hb);
    l = __bfloat16_as_ushort(lb);
}

// ============================ bf16-split GEMM (mma.sync) =====================
// C[M,N] = sum_k A[m,k]*B[n,k]; A,B bf16 hi/lo pairs, K-major rows.
// Block 128x128x32, 256 threads, warp tile 64x32, 2-stage cp.async, 2 CTAs/SM.
// Split terms batched 16-wide to keep dependent HMMAs >=16 apart.
constexpr int BK = 32;
constexpr int LROW80 = 80;                        // smem row stride bytes
constexpr int ARR_BYTES = 128 * LROW80;           // 10240 per operand tile
constexpr int STG_BYTES = 4 * ARR_BYTES;          // Ahi,Alo,Bhi,Blo = 40960
constexpr int SMEM_BYTES = 2 * STG_BYTES;         // 81920 (2 stages)

template <bool BIAS, int OUT>
__global__ __launch_bounds__(256, 2)
void hm_gemm(const unsigned short* __restrict__ Ah, const unsigned short* __restrict__ Al,
             const unsigned short* __restrict__ Bh, const unsigned short* __restrict__ Bl,
             const float* __restrict__ bias, float* __restrict__ C,
             unsigned short* __restrict__ Chi, unsigned short* __restrict__ Clo,
             int Ntot, int Ktot)
{
    extern __shared__ __align__(128) char smem[];
    const uint32_t sb = smem_u32(smem);
    const int tid = threadIdx.x, lane = tid & 31, wid = tid >> 5;
    const int bm = blockIdx.y * 128, bn = blockIdx.x * 128;
    const int wm = (wid >> 2) * 64, wn = (wid & 3) * 32;
    const int nch = Ktot >> 5;

    const int r0 = tid >> 2;            // 0..63
    const int lc = (tid & 3) * 8;       // ushort offset within row

    auto load_stage = [&](int stg, int ch) {
        const uint32_t st = sb + stg * STG_BYTES;
        const size_t ko = (size_t)(ch * BK) + lc;
        cp16(st + 0 * ARR_BYTES + (r0)      * 80 + lc * 2, Ah + (size_t)(bm + r0)      * Ktot + ko);
        cp16(st + 0 * ARR_BYTES + (r0 + 64) * 80 + lc * 2, Ah + (size_t)(bm + r0 + 64) * Ktot + ko);
        cp16(st + 1 * ARR_BYTES + (r0)      * 80 + lc * 2, Al + (size_t)(bm + r0)      * Ktot + ko);
        cp16(st + 1 * ARR_BYTES + (r0 + 64) * 80 + lc * 2, Al + (size_t)(bm + r0 + 64) * Ktot + ko);
        cp16(st + 2 * ARR_BYTES + (r0)      * 80 + lc * 2, Bh + (size_t)(bn + r0)      * Ktot + ko);
        cp16(st + 2 * ARR_BYTES + (r0 + 64) * 80 + lc * 2, Bh + (size_t)(bn + r0 + 64) * Ktot + ko);
        cp16(st + 3 * ARR_BYTES + (r0)      * 80 + lc * 2, Bl + (size_t)(bn + r0)      * Ktot + ko);
        cp16(st + 3 * ARR_BYTES + (r0 + 64) * 80 + lc * 2, Bl + (size_t)(bn + r0 + 64) * Ktot + ko);
        asm volatile("cp.async.commit_group;");
    };

    // ldmatrix lane-address components
    const int sel = lane >> 3, r8 = lane & 7;
    // A quadrants: (m0-7,k0-7),(m8-15,k0-7),(m0-7,k8-15),(m8-15,k8-15)
    const uint32_t aoffA = (uint32_t)((wm + (sel & 1) * 8 + r8) * 80 + (sel >> 1) * 16);
    // B (stored [N,K]): quadrants (n0-7,k0-7),(n0-7,k8-15),(n8-15,k0-7),(n8-15,k8-15)
    const uint32_t aoffB = (uint32_t)((wn + (sel >> 1) * 8 + r8) * 80 + (sel & 1) * 16);

    float acc[4][4][4];
#pragma unroll
    for (int a = 0; a < 4; a++)
#pragma unroll
        for (int b = 0; b < 4; b++)
#pragma unroll
            for (int c = 0; c < 4; c++) acc[a][b][c] = 0.0f;

    load_stage(0, 0);
    if (nch > 1) load_stage(1, 1);

    for (int i = 0; i < nch; i++) {
        asm volatile("cp.async.wait_group 1;");
        __syncthreads();

        const uint32_t st = sb + (i & 1) * STG_BYTES;
        uint32_t af[4][4], bh[4][2], bl[4][2];

        // ================= k16 = 0 =================
        {
            const uint32_t ko = 0;
#pragma unroll
            for (int mt = 0; mt < 4; mt++)
                ldm_x4(af[mt], st + 0 * ARR_BYTES + aoffA + mt * 1280 + ko);
#pragma unroll
            for (int p = 0; p < 2; p++) {
                uint32_t t[4];
                ldm_x4(t, st + 2 * ARR_BYTES + aoffB + p * 1280 + ko);
                bh[2 * p][0] = t[0]; bh[2 * p][1] = t[1];
                bh[2 * p + 1][0] = t[2]; bh[2 * p + 1][1] = t[3];
                ldm_x4(t, st + 3 * ARR_BYTES + aoffB + p * 1280 + ko);
                bl[2 * p][0] = t[0]; bl[2 * p][1] = t[1];
                bl[2 * p + 1][0] = t[2]; bl[2 * p + 1][1] = t[3];
            }
            // 16 independent hi*hi, then 16 hi*lo, then reload lo-A, 16 lo*hi
#pragma unroll
            for (int mt = 0; mt < 4; mt++)
#pragma unroll
                for (int nt = 0; nt < 4; nt++)
                    mma16816(acc[mt][nt], af[mt], bh[nt]);
#pragma unroll
            for (int mt = 0; mt < 4; mt++)
#pragma unroll
                for (int nt = 0; nt < 4; nt++)
                    mma16816(acc[mt][nt], af[mt], bl[nt]);
#pragma unroll
            for (int mt = 0; mt < 4; mt++)
                ldm_x4(af[mt], st + 1 * ARR_BYTES + aoffA + mt * 1280 + ko);
#pragma unroll
            for (int mt = 0; mt < 4; mt++)
#pragma unroll
                for (int nt = 0; nt < 4; nt++)
                    mma16816(acc[mt][nt], af[mt], bh[nt]);
        }
        // ================= k16 = 1 =================
        {
            const uint32_t ko = 32;
#pragma unroll
            for (int mt = 0; mt < 4; mt++)
                ldm_x4(af[mt], st + 0 * ARR_BYTES + aoffA + mt * 1280 + ko);
#pragma unroll
            for (int p = 0; p < 2; p++) {
                uint32_t t[4];
                ldm_x4(t, st + 2 * ARR_BYTES + aoffB + p * 1280 + ko);
                bh[2 * p][0] = t[0]; bh[2 * p][1] = t[1];
                bh[2 * p + 1][0] = t[2]; bh[2 * p + 1][1] = t[3];
                ldm_x4(t, st + 3 * ARR_BYTES + aoffB + p * 1280 + ko);
                bl[2 * p][0] = t[0]; bl[2 * p][1] = t[1];
                bl[2 * p + 1][0] = t[2]; bl[2 * p + 1][1] = t[3];
            }
#pragma unroll
            for (int mt = 0; mt < 4; mt++)
#pragma unroll
                for (int nt = 0; nt < 4; nt++)
                    mma16816(acc[mt][nt], af[mt], bh[nt]);
#pragma unroll
            for (int mt = 0; mt < 4; mt++)
#pragma unroll
                for (int nt = 0; nt < 4; nt++)
                    mma16816(acc[mt][nt], af[mt], bl[nt]);
#pragma unroll
            for (int mt = 0; mt < 4; mt++)
                ldm_x4(af[mt], st + 1 * ARR_BYTES + aoffA + mt * 1280 + ko);

            // last smem read of this stage is done -> barrier here, so the
            // final 16 MMAs + next load issue overlap the barrier shadow
            __syncthreads();

#pragma unroll
            for (int mt = 0; mt < 4; mt++)
#pragma unroll
                for (int nt = 0; nt < 4; nt++)
                    mma16816(acc[mt][nt], af[mt], bh[nt]);
        }
        if (i + 2 < nch) load_stage(i & 1, i + 2);
    }

    // ---- epilogue ----
    const int g = lane >> 2, tg = lane & 3;
#pragma unroll
    for (int mt = 0; mt < 4; mt++) {
#pragma unroll
        for (int nt = 0; nt < 4; nt++) {
            const int m = bm + wm + mt * 16 + g;
            const int n = bn + wn + nt * 8 + tg * 2;
            float bx = 0.f, by = 0.f;
            if (BIAS) { bx = bias[n]; by = bias[n + 1]; }
            float v00 = acc[mt][nt][0] + bx, v01 = acc[mt][nt][1] + by;
            float v10 = acc[mt][nt][2] + bx, v11 = acc[mt][nt][3] + by;
            if (OUT == 0) {
                *reinterpret_cast<float2*>(&C[(size_t)m * Ntot + n]) = make_float2(v00, v01);
                *reinterpret_cast<float2*>(&C[(size_t)(m + 8) * Ntot + n]) = make_float2(v10, v11);
            } else {
                ushort2 h0, l0, h1, l1;
                split1(v00, h0.x, l0.x); split1(v01, h0.y, l0.y);
                split1(v10, h1.x, l1.x); split1(v11, h1.y, l1.y);
                *reinterpret_cast<ushort2*>(&Chi[(size_t)m * Ntot + n]) = h0;
                *reinterpret_cast<ushort2*>(&Clo[(size_t)m * Ntot + n]) = l0;
                *reinterpret_cast<ushort2*>(&Chi[(size_t)(m + 8) * Ntot + n]) = h1;
                *reinterpret_cast<ushort2*>(&Clo[(size_t)(m + 8) * Ntot + n]) = l1;
            }
        }
    }
}

// ============================ split kernels =================================
__global__ __launch_bounds__(256)
void split_dir(const float4* __restrict__ x, ushort4* __restrict__ hi,
               ushort4* __restrict__ lo, size_t n4)
{
    size_t i = (size_t)blockIdx.x * blockDim.x + threadIdx.x;
    if (i >= n4) return;
    float4 v = x[i];
    ushort4 h, l;
    split1(v.x, h.x, l.x);
    split1(v.y, h.y, l.y);
    split1(v.z, h.z, l.z);
    split1(v.w, h.w, l.w);
    hi[i] = h;
    lo[i] = l;
}

// X [R,C] fp32 -> hi/lo [C,R] bf16
__global__ __launch_bounds__(256)
void split_tr(const float* __restrict__ x, unsigned short* __restrict__ hi,
              unsigned short* __restrict__ lo, int R, int C)
{
    __shared__ float t[32][33];
    const int c0 = blockIdx.x * 32, r0 = blockIdx.y * 32;
    const int tx = threadIdx.x, ty = threadIdx.y;  // 32 x 8
#pragma unroll
    for (int j = 0; j < 32; j += 8)
        t[ty + j][tx] = x[(size_t)(r0 + ty + j) * C + c0 + tx];
    __syncthreads();
#pragma unroll
    for (int j = 0; j < 32; j += 8) {
        float v = t[tx][ty + j];
        unsigned short h, l;
        split1(v, h, l);
        size_t o = (size_t)(c0 + ty + j) * R + r0 + tx;
        hi[o] = h;
        lo[o] = l;
    }
}

// ============================ softmax =======================================
__global__ __launch_bounds__(256)
void softmax_rows(float* __restrict__ S)
{
    __shared__ float buf[EE];
    __shared__ float red[256];
    const int row = blockIdx.x;
    const int tid = threadIdx.x;
    float* p = S + (size_t)row * EE;

    float lmax = -INFINITY;
    for (int i = tid; i < EE; i += 256) {
        float v = p[i];
        buf[i] = v;
        lmax = fmaxf(lmax, v);
    }
    red[tid] = lmax;
    __syncthreads();
#pragma unroll
    for (int s = 128; s > 0; s >>= 1) {
        if (tid < s) red[tid] = fmaxf(red[tid], red[tid + s]);
        __syncthreads();
    }
    const float m = red[0];
    __syncthreads();
    float lsum = 0.0f;
    for (int i = tid; i < EE; i += 256) {
        float e = expf(buf[i] - m);
        buf[i] = e;
        lsum += e;
    }
    red[tid] = lsum;
    __syncthreads();
#pragma unroll
    for (int s = 128; s > 0; s >>= 1) {
        if (tid < s) red[tid] += red[tid + s];
        __syncthreads();
    }
    const float inv = 1.0f / red[0];
    for (int i = tid; i < EE; i += 256)
        p[i] = buf[i] * inv;
}

// ============================ host side =====================================
extern "C" void kernel_launch(void* const* d_in, const int* in_sizes, int n_in,
                              void* d_out, int out_size)
{
    const float* tokens = (const float*)d_in[0];
    const float* Wq = (const float*)d_in[1];
    const float* bq = (const float*)d_in[2];
    const float* Wk = (const float*)d_in[3];
    const float* bk = (const float*)d_in[4];
    const float* Wv = (const float*)d_in[5];
    const float* bv = (const float*)d_in[6];
    const float* Wp = (const float*)d_in[7];
    const float* bp = (const float*)d_in[8];
    float* out = (float*)d_out;

    unsigned char* base;
    cudaGetSymbolAddress((void**)&base, g_scratch);
    float* f32tmp = (float*)(base + OFF_F32);   // q -> k fp32
    float* S      = (float*)(base + OFF_S);
#define PU(off) ((unsigned short*)(base + (off)))

    cudaFuncSetAttribute(hm_gemm<true, 0>,  cudaFuncAttributeMaxDynamicSharedMemorySize, SMEM_BYTES);
    cudaFuncSetAttribute(hm_gemm<true, 1>,  cudaFuncAttributeMaxDynamicSharedMemorySize, SMEM_BYTES);
    cudaFuncSetAttribute(hm_gemm<false, 0>, cudaFuncAttributeMaxDynamicSharedMemorySize, SMEM_BYTES);
    cudaFuncSetAttribute(hm_gemm<false, 1>, cudaFuncAttributeMaxDynamicSharedMemorySize, SMEM_BYTES);

    const dim3 blk(256);
    const dim3 tb(32, 8);
    const dim3 gQKV(EE / 128, TT / 128);   // [T,E] outputs
    const dim3 gS(EE / 128, EE / 128);     // [E,E]
    const dim3 gO(TT / 128, EE / 128);     // [E,T]
    const size_t nTE4 = (size_t)TT * EE / 4;
    const unsigned bTE = (unsigned)((nTE4 + 255) / 256);

    // 1. split tokens
    split_dir<<<bTE, 256>>>((const float4*)tokens, (ushort4*)PU(OFF_TOKH),
                            (ushort4*)PU(OFF_TOKL), nTE4);

    // 2. q = tok @ Wq + bq (fp32) ; transpose-split q
    split_tr<<<dim3(EE / 32, EE / 32), tb>>>(Wq, PU(OFF_WH), PU(OFF_WL), EE, EE);
    hm_gemm<true, 0><<<gQKV, blk, SMEM_BYTES>>>(PU(OFF_TOKH), PU(OFF_TOKL),
        PU(OFF_WH), PU(OFF_WL), bq, f32tmp, nullptr, nullptr, EE, EE);
    split_tr<<<dim3(EE / 32, TT / 32), tb>>>(f32tmp, PU(OFF_QTH), PU(OFF_QTL), TT, EE);

    // 3. k = tok @ Wk + bk (fp32) ; transpose-split k
    split_tr<<<dim3(EE / 32, EE / 32), tb>>>(Wk, PU(OFF_WH), PU(OFF_WL), EE, EE);
    hm_gemm<true, 0><<<gQKV, blk, SMEM_BYTES>>>(PU(OFF_TOKH), PU(OFF_TOKL),
        PU(OFF_WH), PU(OFF_WL), bk, f32tmp, nullptr, nullptr, EE, EE);
    split_tr<<<dim3(EE / 32, TT / 32), tb>>>(f32tmp, PU(OFF_KTH), PU(OFF_KTL), TT, EE);

    // 4. v = tok @ Wv + bv -> fused split epilogue
    split_tr<<<dim3(EE / 32, EE / 32), tb>>>(Wv, PU(OFF_WH), PU(OFF_WL), EE, EE);
    hm_gemm<true, 1><<<gQKV, blk, SMEM_BYTES>>>(PU(OFF_TOKH), PU(OFF_TOKL),
        PU(OFF_WH), PU(OFF_WL), bv, nullptr, PU(OFF_VH), PU(OFF_VL), EE, EE);

    // 5. S = q^T @ k : [E,E], K=T ; softmax ; split S
    hm_gemm<false, 0><<<gS, blk, SMEM_BYTES>>>(PU(OFF_QTH), PU(OFF_QTL),
        PU(OFF_KTH), PU(OFF_KTL), nullptr, S, nullptr, nullptr, EE, TT);
    softmax_rows<<<EE, 256>>>(S);
    {
        size_t n4 = (size_t)EE * EE / 4;
        split_dir<<<(unsigned)((n4 + 255) / 256), 256>>>(
            (const float4*)S, (ushort4*)PU(OFF_SH), (ushort4*)PU(OFF_SL), n4);
    }

    // 6. o = S @ v^T : [E,T], K=E -> fused split epilogue
    hm_gemm<false, 1><<<gO, blk, SMEM_BYTES>>>(PU(OFF_SH), PU(OFF_SL),
        PU(OFF_VH), PU(OFF_VL), nullptr, nullptr, PU(OFF_OH), PU(OFF_OL), TT, EE);

    // 7. split Wp ; out = o @ Wp + bp (fp32 to d_out)
    split_tr<<<dim3(TT / 32, TT / 32), tb>>>(Wp, PU(OFF_WPH), PU(OFF_WPL), TT, TT);
    hm_gemm<true, 0><<<gO, blk, SMEM_BYTES>>>(PU(OFF_OH), PU(OFF_OL),
        PU(OFF_WPH), PU(OFF_WPL), bp, out, nullptr, nullptr, TT, TT);
#undef PU
}

// round 12
// speedup vs baseline: 3.9233x; 1.3438x over previous
#include <cuda_runtime.h>
#include <cuda_bf16.h>
#include <math.h>
#include <stdint.h>

#define TT 8192   // sequence length T
#define EE 4096   // embedding E

// ============================ scratch (576MB + vecs, reused) =================
static constexpr size_t MB = 1ull << 20;
// Pool A @0 (128MB): tokT h/l -> Gh/Gl + Uh/Ul -> WpTl
static constexpr size_t OFF_TOKTH = 0,      OFF_TOKTL = 64*MB;
static constexpr size_t OFF_GH    = 0,      OFF_GL    = 32*MB;
static constexpr size_t OFF_UH    = 64*MB,  OFF_UL    = 96*MB;
static constexpr size_t OFF_WPTL  = 0;
// Pool B @128 (64MB): G fp32 -> P1 h/l -> Wv h/l
static constexpr size_t OFF_GF    = 128*MB;
static constexpr size_t OFF_P1H   = 128*MB, OFF_P1L   = 160*MB;
static constexpr size_t OFF_WVH   = 128*MB, OFF_WVL   = 160*MB;
// Pool C @192 (64MB): WqT h/l -> WkT h/l -> att h/l
static constexpr size_t OFF_WQTH  = 192*MB, OFF_WQTL  = 224*MB;
static constexpr size_t OFF_WKTH  = 192*MB, OFF_WKTL  = 224*MB;
static constexpr size_t OFF_ATH   = 192*MB, OFF_ATL   = 224*MB;
// Pool D @256 (64MB): S fp32 / att fp32
static constexpr size_t OFF_S     = 256*MB;
// Pool E @320 (128MB): tok h/l -> WpTh
static constexpr size_t OFF_TOKH  = 320*MB, OFF_TOKL  = 384*MB;
static constexpr size_t OFF_WPTH  = 320*MB;
// Pool F @448 (128MB): o h/l
static constexpr size_t OFF_OH    = 448*MB, OFF_OL    = 512*MB;
// vectors
static constexpr size_t OFF_VS    = 576*MB;            // s [E]
static constexpr size_t OFF_VU    = 576*MB + 16384;    // u [E]
static constexpr size_t OFF_VW    = 576*MB + 32768;    // w [E]
static constexpr size_t OFF_VR    = 576*MB + 49152;    // r [E]
static constexpr size_t TOTAL_SCRATCH = 576*MB + 65536;
__device__ __align__(1024) unsigned char g_scratch[TOTAL_SCRATCH];

// ============================ PTX helpers ===================================
__device__ __forceinline__ uint32_t smem_u32(const void* p) {
    uint32_t a;
    asm("{ .reg .u64 t; cvta.to.shared.u64 t, %1; cvt.u32.u64 %0, t; }" : "=r"(a) : "l"(p));
    return a;
}
__device__ __forceinline__ void cp16(uint32_t s, const void* g) {
    asm volatile("cp.async.cg.shared.global [%0], [%1], 16;" :: "r"(s), "l"(g));
}
__device__ __forceinline__ void ldm_x4(uint32_t* r, uint32_t addr) {
    asm volatile("ldmatrix.sync.aligned.m8n8.x4.shared.b16 {%0,%1,%2,%3}, [%4];"
                 : "=r"(r[0]), "=r"(r[1]), "=r"(r[2]), "=r"(r[3]) : "r"(addr));
}
__device__ __forceinline__ void mma16816(float* c, const uint32_t* a, const uint32_t* b) {
    asm volatile(
        "mma.sync.aligned.m16n8k16.row.col.f32.bf16.bf16.f32 "
        "{%0,%1,%2,%3}, {%4,%5,%6,%7}, {%8,%9}, {%0,%1,%2,%3};"
        : "+f"(c[0]), "+f"(c[1]), "+f"(c[2]), "+f"(c[3])
        : "r"(a[0]), "r"(a[1]), "r"(a[2]), "r"(a[3]), "r"(b[0]), "r"(b[1]));
}

__device__ __forceinline__ void split1(float x, unsigned short& h, unsigned short& l) {
    __nv_bfloat16 hb = __float2bfloat16_rn(x);
    float r = x - __bfloat162float(hb);
    __nv_bfloat16 lb = __float2bfloat16_rn(r);
    h = __bfloat16_as_ushort(hb);
    l = __bfloat16_as_ushort(lb);
}

// ============================ bf16-split GEMM (mma.sync) =====================
// C[M,N] = sum_k A[m,k]*B[n,k]; A,B bf16 hi/lo, K-major. Block 128x128x32,
// 256 threads, warp tile 64x32, 2-stage cp.async, 2 CTAs/SM.
// BMODE: 0 none, 1 col bias (cbias[n]), 2 row bias (rbias[m]).
// OUT:   0 fp32 C, 1 hi/lo split outputs.  TRI: compute only bm>=bn blocks.
constexpr int BK = 32;
constexpr int ARR_BYTES = 128 * 80;
constexpr int STG_BYTES = 4 * ARR_BYTES;
constexpr int SMEM_BYTES = 2 * STG_BYTES;   // 81920

template <int BMODE, int OUT, bool TRI>
__global__ __launch_bounds__(256, 2)
void hm_gemm(const unsigned short* __restrict__ Ah, const unsigned short* __restrict__ Al,
             const unsigned short* __restrict__ Bh, const unsigned short* __restrict__ Bl,
             const float* __restrict__ cbias, const float* __restrict__ rbias,
             float* __restrict__ C,
             unsigned short* __restrict__ Chi, unsigned short* __restrict__ Clo,
             int Ntot, int Ktot)
{
    extern __shared__ __align__(128) char smem[];
    const uint32_t sb = smem_u32(smem);
    const int tid = threadIdx.x, lane = tid & 31, wid = tid >> 5;
    const int bm = blockIdx.y * 128, bn = blockIdx.x * 128;
    if (TRI && bm < bn) return;   // lower triangle only (uniform exit)
    const int wm = (wid >> 2) * 64, wn = (wid & 3) * 32;
    const int nch = Ktot >> 5;

    const int r0 = tid >> 2;
    const int lc = (tid & 3) * 8;

    auto load_stage = [&](int stg, int ch) {
        const uint32_t st = sb + stg * STG_BYTES;
        const size_t ko = (size_t)(ch * BK) + lc;
        cp16(st + 0 * ARR_BYTES + (r0)      * 80 + lc * 2, Ah + (size_t)(bm + r0)      * Ktot + ko);
        cp16(st + 0 * ARR_BYTES + (r0 + 64) * 80 + lc * 2, Ah + (size_t)(bm + r0 + 64) * Ktot + ko);
        cp16(st + 1 * ARR_BYTES + (r0)      * 80 + lc * 2, Al + (size_t)(bm + r0)      * Ktot + ko);
        cp16(st + 1 * ARR_BYTES + (r0 + 64) * 80 + lc * 2, Al + (size_t)(bm + r0 + 64) * Ktot + ko);
        cp16(st + 2 * ARR_BYTES + (r0)      * 80 + lc * 2, Bh + (size_t)(bn + r0)      * Ktot + ko);
        cp16(st + 2 * ARR_BYTES + (r0 + 64) * 80 + lc * 2, Bh + (size_t)(bn + r0 + 64) * Ktot + ko);
        cp16(st + 3 * ARR_BYTES + (r0)      * 80 + lc * 2, Bl + (size_t)(bn + r0)      * Ktot + ko);
        cp16(st + 3 * ARR_BYTES + (r0 + 64) * 80 + lc * 2, Bl + (size_t)(bn + r0 + 64) * Ktot + ko);
        asm volatile("cp.async.commit_group;");
    };

    const int sel = lane >> 3, r8 = lane & 7;
    const uint32_t aoffA = (uint32_t)((wm + (sel & 1) * 8 + r8) * 80 + (sel >> 1) * 16);
    const uint32_t aoffB = (uint32_t)((wn + (sel >> 1) * 8 + r8) * 80 + (sel & 1) * 16);

    float acc[4][4][4];
#pragma unroll
    for (int a = 0; a < 4; a++)
#pragma unroll
        for (int b = 0; b < 4; b++)
#pragma unroll
            for (int c = 0; c < 4; c++) acc[a][b][c] = 0.0f;

    load_stage(0, 0);
    if (nch > 1) load_stage(1, 1);

    for (int i = 0; i < nch; i++) {
        asm volatile("cp.async.wait_group 1;");
        __syncthreads();

        const uint32_t st = sb + (i & 1) * STG_BYTES;
        uint32_t af[4][4], bh[4][2], bl[4][2];

        // ---- k16 = 0 ----
        {
            const uint32_t ko = 0;
#pragma unroll
            for (int mt = 0; mt < 4; mt++)
                ldm_x4(af[mt], st + 0 * ARR_BYTES + aoffA + mt * 1280 + ko);
#pragma unroll
            for (int p = 0; p < 2; p++) {
                uint32_t t[4];
                ldm_x4(t, st + 2 * ARR_BYTES + aoffB + p * 1280 + ko);
                bh[2 * p][0] = t[0]; bh[2 * p][1] = t[1];
                bh[2 * p + 1][0] = t[2]; bh[2 * p + 1][1] = t[3];
                ldm_x4(t, st + 3 * ARR_BYTES + aoffB + p * 1280 + ko);
                bl[2 * p][0] = t[0]; bl[2 * p][1] = t[1];
                bl[2 * p + 1][0] = t[2]; bl[2 * p + 1][1] = t[3];
            }
#pragma unroll
            for (int mt = 0; mt < 4; mt++)
#pragma unroll
                for (int nt = 0; nt < 4; nt++)
                    mma16816(acc[mt][nt], af[mt], bh[nt]);
#pragma unroll
            for (int mt = 0; mt < 4; mt++)
#pragma unroll
                for (int nt = 0; nt < 4; nt++)
                    mma16816(acc[mt][nt], af[mt], bl[nt]);
#pragma unroll
            for (int mt = 0; mt < 4; mt++)
                ldm_x4(af[mt], st + 1 * ARR_BYTES + aoffA + mt * 1280 + ko);
#pragma unroll
            for (int mt = 0; mt < 4; mt++)
#pragma unroll
                for (int nt = 0; nt < 4; nt++)
                    mma16816(acc[mt][nt], af[mt], bh[nt]);
        }
        // ---- k16 = 1 ----
        {
            const uint32_t ko = 32;
#pragma unroll
            for (int mt = 0; mt < 4; mt++)
                ldm_x4(af[mt], st + 0 * ARR_BYTES + aoffA + mt * 1280 + ko);
#pragma unroll
            for (int p = 0; p < 2; p++) {
                uint32_t t[4];
                ldm_x4(t, st + 2 * ARR_BYTES + aoffB + p * 1280 + ko);
                bh[2 * p][0] = t[0]; bh[2 * p][1] = t[1];
                bh[2 * p + 1][0] = t[2]; bh[2 * p + 1][1] = t[3];
                ldm_x4(t, st + 3 * ARR_BYTES + aoffB + p * 1280 + ko);
                bl[2 * p][0] = t[0]; bl[2 * p][1] = t[1];
                bl[2 * p + 1][0] = t[2]; bl[2 * p + 1][1] = t[3];
            }
#pragma unroll
            for (int mt = 0; mt < 4; mt++)
#pragma unroll
                for (int nt = 0; nt < 4; nt++)
                    mma16816(acc[mt][nt], af[mt], bh[nt]);
#pragma unroll
            for (int mt = 0; mt < 4; mt++)
#pragma unroll
                for (int nt = 0; nt < 4; nt++)
                    mma16816(acc[mt][nt], af[mt], bl[nt]);
#pragma unroll
            for (int mt = 0; mt < 4; mt++)
                ldm_x4(af[mt], st + 1 * ARR_BYTES + aoffA + mt * 1280 + ko);

            __syncthreads();   // stage fully read; final MMAs overlap barrier

#pragma unroll
            for (int mt = 0; mt < 4; mt++)
#pragma unroll
                for (int nt = 0; nt < 4; nt++)
                    mma16816(acc[mt][nt], af[mt], bh[nt]);
        }
        if (i + 2 < nch) load_stage(i & 1, i + 2);
    }

    // ---- epilogue ----
    const int g = lane >> 2, tg = lane & 3;
#pragma unroll
    for (int mt = 0; mt < 4; mt++) {
#pragma unroll
        for (int nt = 0; nt < 4; nt++) {
            const int m = bm + wm + mt * 16 + g;
            const int n = bn + wn + nt * 8 + tg * 2;
            float c0 = 0.f, c1 = 0.f, rr0 = 0.f, rr1 = 0.f;
            if (BMODE == 1) { c0 = cbias[n]; c1 = cbias[n + 1]; }
            if (BMODE == 2) { rr0 = rbias[m]; rr1 = rbias[m + 8]; }
            float v00 = acc[mt][nt][0] + c0 + rr0, v01 = acc[mt][nt][1] + c1 + rr0;
            float v10 = acc[mt][nt][2] + c0 + rr1, v11 = acc[mt][nt][3] + c1 + rr1;
            if (OUT == 0) {
                *reinterpret_cast<float2*>(&C[(size_t)m * Ntot + n]) = make_float2(v00, v01);
                *reinterpret_cast<float2*>(&C[(size_t)(m + 8) * Ntot + n]) = make_float2(v10, v11);
            } else {
                ushort2 h0, l0, h1, l1;
                split1(v00, h0.x, l0.x); split1(v01, h0.y, l0.y);
                split1(v10, h1.x, l1.x); split1(v11, h1.y, l1.y);
                *reinterpret_cast<ushort2*>(&Chi[(size_t)m * Ntot + n]) = h0;
                *reinterpret_cast<ushort2*>(&Clo[(size_t)m * Ntot + n]) = l0;
                *reinterpret_cast<ushort2*>(&Chi[(size_t)(m + 8) * Ntot + n]) = h1;
                *reinterpret_cast<ushort2*>(&Clo[(size_t)(m + 8) * Ntot + n]) = l1;
            }
        }
    }
}

// ============================ aux kernels ===================================
__global__ __launch_bounds__(256)
void split_dir(const float4* __restrict__ x, ushort4* __restrict__ hi,
               ushort4* __restrict__ lo, size_t n4)
{
    size_t i = (size_t)blockIdx.x * blockDim.x + threadIdx.x;
    if (i >= n4) return;
    float4 v = x[i];
    ushort4 h, l;
    split1(v.x, h.x, l.x); split1(v.y, h.y, l.y);
    split1(v.z, h.z, l.z); split1(v.w, h.w, l.w);
    hi[i] = h; lo[i] = l;
}

// X [R,C] fp32 -> hi/lo [C,R] bf16   (launch with (32,8) block!)
__global__ __launch_bounds__(256)
void split_tr(const float* __restrict__ x, unsigned short* __restrict__ hi,
              unsigned short* __restrict__ lo, int R, int C)
{
    __shared__ float t[32][33];
    const int c0 = blockIdx.x * 32, r0 = blockIdx.y * 32;
    const int tx = threadIdx.x, ty = threadIdx.y;
#pragma unroll
    for (int j = 0; j < 32; j += 8)
        t[ty + j][tx] = x[(size_t)(r0 + ty + j) * C + c0 + tx];
    __syncthreads();
#pragma unroll
    for (int j = 0; j < 32; j += 8) {
        float v = t[tx][ty + j];
        unsigned short h, l;
        split1(v, h, l);
        size_t o = (size_t)(c0 + ty + j) * R + r0 + tx;
        hi[o] = h; lo[o] = l;
    }
}

// mirror lower triangle of G [E,E] to upper (32x32 tiles; (32,8) block!)
__global__ __launch_bounds__(256)
void mirror_upper(float* __restrict__ G)
{
    const int txb = blockIdx.x, tyb = blockIdx.y;
    if (txb <= tyb) return;                 // only strict-lower source tiles
    __shared__ float t[32][33];
    const int sr = txb * 32, sc = tyb * 32; // source: rows sr (low), cols sc
    const int tx = threadIdx.x, ty = threadIdx.y;
#pragma unroll
    for (int j = 0; j < 32; j += 8)
        t[ty + j][tx] = G[(size_t)(sr + ty + j) * EE + sc + tx];
    __syncthreads();
#pragma unroll
    for (int j = 0; j < 32; j += 8)
        G[(size_t)(sc + ty + j) * EE + sr + tx] = t[tx][ty + j];
}

// s[e] = sum_t X[t,e]   (atomic partials; s pre-zeroed)
__global__ __launch_bounds__(256)
void colsum_kernel(const float* __restrict__ X, float* __restrict__ s)
{
    const int e = blockIdx.x * 256 + threadIdx.x;
    const int t0 = blockIdx.y * (TT / 32);
    float acc = 0.f;
    for (int t = t0; t < t0 + TT / 32; t++) acc += X[(size_t)t * EE + e];
    atomicAdd(&s[e], acc);
}

// out[m] += sum_k W[k,m]*s[k]  (atomic partials; out pre-zeroed)
__global__ __launch_bounds__(256)
void gemv_tn(const float* __restrict__ W, const float* __restrict__ s,
             float* __restrict__ out)
{
    const int m = blockIdx.x * 256 + threadIdx.x;
    const int k0 = blockIdx.y * 256;
    float acc = 0.f;
    for (int k = k0; k < k0 + 256; k++) acc += W[(size_t)k * EE + m] * s[k];
    atomicAdd(&out[m], acc);
}

// out[m] = sum_e A[m,e]*x[e]   (warp per row)
__global__ __launch_bounds__(256)
void gemv_nn(const float* __restrict__ A, const float* __restrict__ x,
             float* __restrict__ out)
{
    const int row = blockIdx.x * 8 + (threadIdx.x >> 5);
    const int lane = threadIdx.x & 31;
    const float* p = A + (size_t)row * EE;
    float acc = 0.f;
    for (int e = lane; e < EE; e += 32) acc += p[e] * x[e];
#pragma unroll
    for (int o = 16; o > 0; o >>= 1) acc += __shfl_down_sync(~0u, acc, o);
    if (lane == 0) out[row] = acc;
}

// softmax rows with rank-1 bias terms:
// logit = S + u[row]*bk[col] + bq[row]*(w[col] + T*bk[col])
__global__ __launch_bounds__(256)
void softmax_rank1(float* __restrict__ S, const float* __restrict__ u,
                   const float* __restrict__ w, const float* __restrict__ bq,
                   const float* __restrict__ bk)
{
    __shared__ float buf[EE];
    __shared__ float red[256];
    const int row = blockIdx.x;
    const int tid = threadIdx.x;
    float* p = S + (size_t)row * EE;
    const float ur = u[row], br = bq[row];

    float lmax = -INFINITY;
    for (int i = tid; i < EE; i += 256) {
        float v = p[i] + ur * bk[i] + br * (w[i] + (float)TT * bk[i]);
        buf[i] = v;
        lmax = fmaxf(lmax, v);
    }
    red[tid] = lmax;
    __syncthreads();
#pragma unroll
    for (int s = 128; s > 0; s >>= 1) {
        if (tid < s) red[tid] = fmaxf(red[tid], red[tid + s]);
        __syncthreads();
    }
    const float m = red[0];
    __syncthreads();
    float lsum = 0.f;
    for (int i = tid; i < EE; i += 256) {
        float e = expf(buf[i] - m);
        buf[i] = e;
        lsum += e;
    }
    red[tid] = lsum;
    __syncthreads();
#pragma unroll
    for (int s = 128; s > 0; s >>= 1) {
        if (tid < s) red[tid] += red[tid + s];
        __syncthreads();
    }
    const float inv = 1.0f / red[0];
    for (int i = tid; i < EE; i += 256)
        p[i] = buf[i] * inv;
}

// ============================ host side =====================================
extern "C" void kernel_launch(void* const* d_in, const int* in_sizes, int n_in,
                              void* d_out, int out_size)
{
    const float* tokens = (const float*)d_in[0];
    const float* Wq = (const float*)d_in[1];
    const float* bq = (const float*)d_in[2];
    const float* Wk = (const float*)d_in[3];
    const float* bk = (const float*)d_in[4];
    const float* Wv = (const float*)d_in[5];
    const float* bv = (const float*)d_in[6];
    const float* Wp = (const float*)d_in[7];
    const float* bp = (const float*)d_in[8];
    float* out = (float*)d_out;

    unsigned char* base;
    cudaGetSymbolAddress((void**)&base, g_scratch);
#define PF(off) ((float*)(base + (off)))
#define PU(off) ((unsigned short*)(base + (off)))

    cudaFuncSetAttribute(hm_gemm<0,0,true>,  cudaFuncAttributeMaxDynamicSharedMemorySize, SMEM_BYTES);
    cudaFuncSetAttribute(hm_gemm<0,0,false>, cudaFuncAttributeMaxDynamicSharedMemorySize, SMEM_BYTES);
    cudaFuncSetAttribute(hm_gemm<0,1,false>, cudaFuncAttributeMaxDynamicSharedMemorySize, SMEM_BYTES);
    cudaFuncSetAttribute(hm_gemm<2,1,false>, cudaFuncAttributeMaxDynamicSharedMemorySize, SMEM_BYTES);
    cudaFuncSetAttribute(hm_gemm<1,0,false>, cudaFuncAttributeMaxDynamicSharedMemorySize, SMEM_BYTES);

    const dim3 blk(256), tb(32, 8);
    float* s = PF(OFF_VS); float* u = PF(OFF_VU);
    float* w = PF(OFF_VW); float* r = PF(OFF_VR);

    // 0. zero s,u,w (atomic accumulators)
    cudaMemsetAsync(base + OFF_VS, 0, 49152);

    // 1. s = colsum(X) ; tokT split
    colsum_kernel<<<dim3(EE / 256, 32), blk>>>(tokens, s);
    split_tr<<<dim3(EE / 32, TT / 32), tb>>>(tokens, PU(OFF_TOKTH), PU(OFF_TOKTL), TT, EE);

    // 2. G = X^T X (lower triangle), mirror, split
    hm_gemm<0,0,true><<<dim3(EE/128, EE/128), blk, SMEM_BYTES>>>(
        PU(OFF_TOKTH), PU(OFF_TOKTL), PU(OFF_TOKTH), PU(OFF_TOKTL),
        nullptr, nullptr, PF(OFF_GF), nullptr, nullptr, EE, TT);
    mirror_upper<<<dim3(EE/32, EE/32), tb>>>(PF(OFF_GF));
    {
        size_t n4 = (size_t)EE * EE / 4;
        split_dir<<<(unsigned)((n4 + 255) / 256), blk>>>(
            (const float4*)PF(OFF_GF), (ushort4*)PU(OFF_GH), (ushort4*)PU(OFF_GL), n4);
    }

    // 3. P1 = Wq^T G  (fused split out) ; u = Wq^T s
    split_tr<<<dim3(EE / 32, EE / 32), tb>>>(Wq, PU(OFF_WQTH), PU(OFF_WQTL), EE, EE);
    gemv_tn<<<dim3(EE / 256, EE / 256), blk>>>(Wq, s, u);
    hm_gemm<0,1,false><<<dim3(EE/128, EE/128), blk, SMEM_BYTES>>>(
        PU(OFF_WQTH), PU(OFF_WQTL), PU(OFF_GH), PU(OFF_GL),
        nullptr, nullptr, nullptr, PU(OFF_P1H), PU(OFF_P1L), EE, EE);

    // 4. S = P1 Wk ; w = Wk^T s
    split_tr<<<dim3(EE / 32, EE / 32), tb>>>(Wk, PU(OFF_WKTH), PU(OFF_WKTL), EE, EE);
    gemv_tn<<<dim3(EE / 256, EE / 256), blk>>>(Wk, s, w);
    hm_gemm<0,0,false><<<dim3(EE/128, EE/128), blk, SMEM_BYTES>>>(
        PU(OFF_P1H), PU(OFF_P1L), PU(OFF_WKTH), PU(OFF_WKTL),
        nullptr, nullptr, PF(OFF_S), nullptr, nullptr, EE, EE);

    // 5. softmax (+rank-1 bias terms) ; r = att bv ; split att
    softmax_rank1<<<EE, blk>>>(PF(OFF_S), u, w, bq, bk);
    gemv_nn<<<EE / 8, blk>>>(PF(OFF_S), bv, r);
    {
        size_t n4 = (size_t)EE * EE / 4;
        split_dir<<<(unsigned)((n4 + 255) / 256), blk>>>(
            (const float4*)PF(OFF_S), (ushort4*)PU(OFF_ATH), (ushort4*)PU(OFF_ATL), n4);
    }

    // 6. U = att Wv^T (fused split out);  Wv used direct (B[n,k]=Wv[n,k])
    {
        size_t n4 = (size_t)EE * EE / 4;
        split_dir<<<(unsigned)((n4 + 255) / 256), blk>>>(
            (const float4*)Wv, (ushort4*)PU(OFF_WVH), (ushort4*)PU(OFF_WVL), n4);
    }
    hm_gemm<0,1,false><<<dim3(EE/128, EE/128), blk, SMEM_BYTES>>>(
        PU(OFF_ATH), PU(OFF_ATL), PU(OFF_WVH), PU(OFF_WVL),
        nullptr, nullptr, nullptr, PU(OFF_UH), PU(OFF_UL), EE, EE);

    // 7. o = U X^T + r 1^T (fused split out); tokens direct split for B
    {
        size_t n4 = (size_t)TT * EE / 4;
        split_dir<<<(unsigned)((n4 + 255) / 256), blk>>>(
            (const float4*)tokens, (ushort4*)PU(OFF_TOKH), (ushort4*)PU(OFF_TOKL), n4);
    }
    hm_gemm<2,1,false><<<dim3(TT/128, EE/128), blk, SMEM_BYTES>>>(
        PU(OFF_UH), PU(OFF_UL), PU(OFF_TOKH), PU(OFF_TOKL),
        nullptr, r, nullptr, PU(OFF_OH), PU(OFF_OL), TT, EE);

    // 8. out = o Wp + bp
    split_tr<<<dim3(TT / 32, TT / 32), tb>>>(Wp, PU(OFF_WPTH), PU(OFF_WPTL), TT, TT);
    hm_gemm<1,0,false><<<dim3(TT/128, EE/128), blk, SMEM_BYTES>>>(
        PU(OFF_OH), PU(OFF_OL), PU(OFF_WPTH), PU(OFF_WPTL),
        bp, nullptr, out, nullptr, nullptr, TT, TT);
#undef PF
#undef PU
}

// round 13
// speedup vs baseline: 4.7824x; 1.2190x over previous
#include <cuda_runtime.h>
#include <cuda_bf16.h>
#include <cuda_fp16.h>
#include <math.h>
#include <stdint.h>

#define TT 8192   // sequence length T
#define EE 4096   // embedding E

// ============================ scratch (576MB + vecs, reused) =================
static constexpr size_t MB = 1ull << 20;
// Pool A @0 (128MB): tokT h/l -> Gh/Gl + Uh/Ul -> WpTl
static constexpr size_t OFF_TOKTH = 0,      OFF_TOKTL = 64*MB;
static constexpr size_t OFF_GH    = 0,      OFF_GL    = 32*MB;
static constexpr size_t OFF_UH    = 64*MB,  OFF_UL    = 96*MB;
static constexpr size_t OFF_WPTL  = 0;
// Pool B @128 (64MB): G fp32 -> P1 h/l -> Wv h/l
static constexpr size_t OFF_GF    = 128*MB;
static constexpr size_t OFF_P1H   = 128*MB, OFF_P1L   = 160*MB;
static constexpr size_t OFF_WVH   = 128*MB, OFF_WVL   = 160*MB;
// Pool C @192 (64MB): WqT h/l -> WkT h/l -> att h/l
static constexpr size_t OFF_WQTH  = 192*MB, OFF_WQTL  = 224*MB;
static constexpr size_t OFF_WKTH  = 192*MB, OFF_WKTL  = 224*MB;
static constexpr size_t OFF_ATH   = 192*MB, OFF_ATL   = 224*MB;
// Pool D @256 (64MB): S fp32 / att fp32
static constexpr size_t OFF_S     = 256*MB;
// Pool E @320 (128MB): tok h/l -> WpTh
static constexpr size_t OFF_TOKH  = 320*MB, OFF_TOKL  = 384*MB;
static constexpr size_t OFF_WPTH  = 320*MB;
// Pool F @448 (128MB): o h/l
static constexpr size_t OFF_OH    = 448*MB, OFF_OL    = 512*MB;
// vectors
static constexpr size_t OFF_VS    = 576*MB;            // s [E]
static constexpr size_t OFF_VU    = 576*MB + 16384;    // u [E]
static constexpr size_t OFF_VW    = 576*MB + 32768;    // w [E]
static constexpr size_t OFF_VR    = 576*MB + 49152;    // r [E]
static constexpr size_t TOTAL_SCRATCH = 576*MB + 65536;
__device__ __align__(1024) unsigned char g_scratch[TOTAL_SCRATCH];

// ============================ PTX helpers ===================================
__device__ __forceinline__ uint32_t smem_u32(const void* p) {
    uint32_t a;
    asm("{ .reg .u64 t; cvta.to.shared.u64 t, %1; cvt.u32.u64 %0, t; }" : "=r"(a) : "l"(p));
    return a;
}
__device__ __forceinline__ void cp16(uint32_t s, const void* g) {
    asm volatile("cp.async.cg.shared.global [%0], [%1], 16;" :: "r"(s), "l"(g));
}
__device__ __forceinline__ void ldm_x4(uint32_t* r, uint32_t addr) {
    asm volatile("ldmatrix.sync.aligned.m8n8.x4.shared.b16 {%0,%1,%2,%3}, [%4];"
                 : "=r"(r[0]), "=r"(r[1]), "=r"(r[2]), "=r"(r[3]) : "r"(addr));
}
// fp16 inputs, fp32 accumulate
__device__ __forceinline__ void mma16816(float* c, const uint32_t* a, const uint32_t* b) {
    asm volatile(
        "mma.sync.aligned.m16n8k16.row.col.f32.f16.f16.f32 "
        "{%0,%1,%2,%3}, {%4,%5,%6,%7}, {%8,%9}, {%0,%1,%2,%3};"
        : "+f"(c[0]), "+f"(c[1]), "+f"(c[2]), "+f"(c[3])
        : "r"(a[0]), "r"(a[1]), "r"(a[2]), "r"(a[3]), "r"(b[0]), "r"(b[1]));
}

// fp16 hi/lo split: effective ~22-bit mantissa across the pair
__device__ __forceinline__ void split1(float x, unsigned short& h, unsigned short& l) {
    __half hb = __float2half_rn(x);
    float r = x - __half2float(hb);
    __half lb = __float2half_rn(r);
    h = __half_as_ushort(hb);
    l = __half_as_ushort(lb);
}

// ============================ fp16-split GEMM (mma.sync) =====================
// C[M,N] = sum_k A[m,k]*B[n,k]; A,B fp16 hi/lo, K-major. Block 128x128x32,
// 256 threads, warp tile 64x32, 2-stage cp.async, 2 CTAs/SM.
// BMODE: 0 none, 1 col bias (cbias[n]), 2 row bias (rbias[m]).
// OUT:   0 fp32 C, 1 hi/lo split outputs.  TRI: only bm>=bn blocks.
// NT:    3 = hi*hi + hi*lo + lo*hi;  2 = hi*hi + hi*lo (A-lo never loaded).
constexpr int BK = 32;
constexpr int ARR_BYTES = 128 * 80;
constexpr int STG_BYTES = 4 * ARR_BYTES;
constexpr int SMEM_BYTES = 2 * STG_BYTES;   // 81920

template <int BMODE, int OUT, bool TRI, int NT>
__global__ __launch_bounds__(256, 2)
void hm_gemm(const unsigned short* __restrict__ Ah, const unsigned short* __restrict__ Al,
             const unsigned short* __restrict__ Bh, const unsigned short* __restrict__ Bl,
             const float* __restrict__ cbias, const float* __restrict__ rbias,
             float* __restrict__ C,
             unsigned short* __restrict__ Chi, unsigned short* __restrict__ Clo,
             int Ntot, int Ktot)
{
    extern __shared__ __align__(128) char smem[];
    const uint32_t sb = smem_u32(smem);
    const int tid = threadIdx.x, lane = tid & 31, wid = tid >> 5;
    const int bm = blockIdx.y * 128, bn = blockIdx.x * 128;
    if (TRI && bm < bn) return;   // lower triangle only (uniform exit)
    const int wm = (wid >> 2) * 64, wn = (wid & 3) * 32;
    const int nch = Ktot >> 5;

    const int r0 = tid >> 2;
    const int lc = (tid & 3) * 8;

    auto load_stage = [&](int stg, int ch) {
        const uint32_t st = sb + stg * STG_BYTES;
        const size_t ko = (size_t)(ch * BK) + lc;
        cp16(st + 0 * ARR_BYTES + (r0)      * 80 + lc * 2, Ah + (size_t)(bm + r0)      * Ktot + ko);
        cp16(st + 0 * ARR_BYTES + (r0 + 64) * 80 + lc * 2, Ah + (size_t)(bm + r0 + 64) * Ktot + ko);
        if (NT == 3) {
            cp16(st + 1 * ARR_BYTES + (r0)      * 80 + lc * 2, Al + (size_t)(bm + r0)      * Ktot + ko);
            cp16(st + 1 * ARR_BYTES + (r0 + 64) * 80 + lc * 2, Al + (size_t)(bm + r0 + 64) * Ktot + ko);
        }
        cp16(st + 2 * ARR_BYTES + (r0)      * 80 + lc * 2, Bh + (size_t)(bn + r0)      * Ktot + ko);
        cp16(st + 2 * ARR_BYTES + (r0 + 64) * 80 + lc * 2, Bh + (size_t)(bn + r0 + 64) * Ktot + ko);
        cp16(st + 3 * ARR_BYTES + (r0)      * 80 + lc * 2, Bl + (size_t)(bn + r0)      * Ktot + ko);
        cp16(st + 3 * ARR_BYTES + (r0 + 64) * 80 + lc * 2, Bl + (size_t)(bn + r0 + 64) * Ktot + ko);
        asm volatile("cp.async.commit_group;");
    };

    const int sel = lane >> 3, r8 = lane & 7;
    const uint32_t aoffA = (uint32_t)((wm + (sel & 1) * 8 + r8) * 80 + (sel >> 1) * 16);
    const uint32_t aoffB = (uint32_t)((wn + (sel >> 1) * 8 + r8) * 80 + (sel & 1) * 16);

    float acc[4][4][4];
#pragma unroll
    for (int a = 0; a < 4; a++)
#pragma unroll
        for (int b = 0; b < 4; b++)
#pragma unroll
            for (int c = 0; c < 4; c++) acc[a][b][c] = 0.0f;

    load_stage(0, 0);
    if (nch > 1) load_stage(1, 1);

    for (int i = 0; i < nch; i++) {
        asm volatile("cp.async.wait_group 1;");
        __syncthreads();

        const uint32_t st = sb + (i & 1) * STG_BYTES;
        uint32_t af[4][4], bh[4][2], bl[4][2];

        // ---- k16 = 0 ----
        {
            const uint32_t ko = 0;
#pragma unroll
            for (int mt = 0; mt < 4; mt++)
                ldm_x4(af[mt], st + 0 * ARR_BYTES + aoffA + mt * 1280 + ko);
#pragma unroll
            for (int p = 0; p < 2; p++) {
                uint32_t t[4];
                ldm_x4(t, st + 2 * ARR_BYTES + aoffB + p * 1280 + ko);
                bh[2 * p][0] = t[0]; bh[2 * p][1] = t[1];
                bh[2 * p + 1][0] = t[2]; bh[2 * p + 1][1] = t[3];
                ldm_x4(t, st + 3 * ARR_BYTES + aoffB + p * 1280 + ko);
                bl[2 * p][0] = t[0]; bl[2 * p][1] = t[1];
                bl[2 * p + 1][0] = t[2]; bl[2 * p + 1][1] = t[3];
            }
#pragma unroll
            for (int mt = 0; mt < 4; mt++)
#pragma unroll
                for (int nt = 0; nt < 4; nt++)
                    mma16816(acc[mt][nt], af[mt], bh[nt]);
#pragma unroll
            for (int mt = 0; mt < 4; mt++)
#pragma unroll
                for (int nt = 0; nt < 4; nt++)
                    mma16816(acc[mt][nt], af[mt], bl[nt]);
            if (NT == 3) {
#pragma unroll
                for (int mt = 0; mt < 4; mt++)
                    ldm_x4(af[mt], st + 1 * ARR_BYTES + aoffA + mt * 1280 + ko);
#pragma unroll
                for (int mt = 0; mt < 4; mt++)
#pragma unroll
                    for (int nt = 0; nt < 4; nt++)
                        mma16816(acc[mt][nt], af[mt], bh[nt]);
            }
        }
        // ---- k16 = 1 ----
        {
            const uint32_t ko = 32;
#pragma unroll
            for (int mt = 0; mt < 4; mt++)
                ldm_x4(af[mt], st + 0 * ARR_BYTES + aoffA + mt * 1280 + ko);
#pragma unroll
            for (int p = 0; p < 2; p++) {
                uint32_t t[4];
                ldm_x4(t, st + 2 * ARR_BYTES + aoffB + p * 1280 + ko);
                bh[2 * p][0] = t[0]; bh[2 * p][1] = t[1];
                bh[2 * p + 1][0] = t[2]; bh[2 * p + 1][1] = t[3];
                ldm_x4(t, st + 3 * ARR_BYTES + aoffB + p * 1280 + ko);
                bl[2 * p][0] = t[0]; bl[2 * p][1] = t[1];
                bl[2 * p + 1][0] = t[2]; bl[2 * p + 1][1] = t[3];
            }
            if (NT == 3) {
#pragma unroll
                for (int mt = 0; mt < 4; mt++)
#pragma unroll
                    for (int nt = 0; nt < 4; nt++)
                        mma16816(acc[mt][nt], af[mt], bh[nt]);
#pragma unroll
                for (int mt = 0; mt < 4; mt++)
#pragma unroll
                    for (int nt = 0; nt < 4; nt++)
                        mma16816(acc[mt][nt], af[mt], bl[nt]);
#pragma unroll
                for (int mt = 0; mt < 4; mt++)
                    ldm_x4(af[mt], st + 1 * ARR_BYTES + aoffA + mt * 1280 + ko);

                __syncthreads();   // stage fully read; final MMAs overlap barrier

#pragma unroll
                for (int mt = 0; mt < 4; mt++)
#pragma unroll
                    for (int nt = 0; nt < 4; nt++)
                        mma16816(acc[mt][nt], af[mt], bh[nt]);
            } else {
                __syncthreads();   // all smem reads done (frags in regs)
#pragma unroll
                for (int mt = 0; mt < 4; mt++)
#pragma unroll
                    for (int nt = 0; nt < 4; nt++)
                        mma16816(acc[mt][nt], af[mt], bh[nt]);
#pragma unroll
                for (int mt = 0; mt < 4; mt++)
#pragma unroll
                    for (int nt = 0; nt < 4; nt++)
                        mma16816(acc[mt][nt], af[mt], bl[nt]);
            }
        }
        if (i + 2 < nch) load_stage(i & 1, i + 2);
    }

    // ---- epilogue ----
    const int g = lane >> 2, tg = lane & 3;
#pragma unroll
    for (int mt = 0; mt < 4; mt++) {
#pragma unroll
        for (int nt = 0; nt < 4; nt++) {
            const int m = bm + wm + mt * 16 + g;
            const int n = bn + wn + nt * 8 + tg * 2;
            float c0 = 0.f, c1 = 0.f, rr0 = 0.f, rr1 = 0.f;
            if (BMODE == 1) { c0 = cbias[n]; c1 = cbias[n + 1]; }
            if (BMODE == 2) { rr0 = rbias[m]; rr1 = rbias[m + 8]; }
            float v00 = acc[mt][nt][0] + c0 + rr0, v01 = acc[mt][nt][1] + c1 + rr0;
            float v10 = acc[mt][nt][2] + c0 + rr1, v11 = acc[mt][nt][3] + c1 + rr1;
            if (OUT == 0) {
                *reinterpret_cast<float2*>(&C[(size_t)m * Ntot + n]) = make_float2(v00, v01);
                *reinterpret_cast<float2*>(&C[(size_t)(m + 8) * Ntot + n]) = make_float2(v10, v11);
            } else {
                ushort2 h0, l0, h1, l1;
                split1(v00, h0.x, l0.x); split1(v01, h0.y, l0.y);
                split1(v10, h1.x, l1.x); split1(v11, h1.y, l1.y);
                *reinterpret_cast<ushort2*>(&Chi[(size_t)m * Ntot + n]) = h0;
                *reinterpret_cast<ushort2*>(&Clo[(size_t)m * Ntot + n]) = l0;
                *reinterpret_cast<ushort2*>(&Chi[(size_t)(m + 8) * Ntot + n]) = h1;
                *reinterpret_cast<ushort2*>(&Clo[(size_t)(m + 8) * Ntot + n]) = l1;
            }
        }
    }
}

// ============================ aux kernels ===================================
__global__ __launch_bounds__(256)
void split_dir(const float4* __restrict__ x, ushort4* __restrict__ hi,
               ushort4* __restrict__ lo, size_t n4)
{
    size_t i = (size_t)blockIdx.x * blockDim.x + threadIdx.x;
    if (i >= n4) return;
    float4 v = x[i];
    ushort4 h, l;
    split1(v.x, h.x, l.x); split1(v.y, h.y, l.y);
    split1(v.z, h.z, l.z); split1(v.w, h.w, l.w);
    hi[i] = h; lo[i] = l;
}

// X [R,C] fp32 -> hi/lo [C,R] fp16   (launch with (32,8) block!)
__global__ __launch_bounds__(256)
void split_tr(const float* __restrict__ x, unsigned short* __restrict__ hi,
              unsigned short* __restrict__ lo, int R, int C)
{
    __shared__ float t[32][33];
    const int c0 = blockIdx.x * 32, r0 = blockIdx.y * 32;
    const int tx = threadIdx.x, ty = threadIdx.y;
#pragma unroll
    for (int j = 0; j < 32; j += 8)
        t[ty + j][tx] = x[(size_t)(r0 + ty + j) * C + c0 + tx];
    __syncthreads();
#pragma unroll
    for (int j = 0; j < 32; j += 8) {
        float v = t[tx][ty + j];
        unsigned short h, l;
        split1(v, h, l);
        size_t o = (size_t)(c0 + ty + j) * R + r0 + tx;
        hi[o] = h; lo[o] = l;
    }
}

// mirror lower triangle of G [E,E] to upper (32x32 tiles; (32,8) block!)
__global__ __launch_bounds__(256)
void mirror_upper(float* __restrict__ G)
{
    const int txb = blockIdx.x, tyb = blockIdx.y;
    if (txb <= tyb) return;
    __shared__ float t[32][33];
    const int sr = txb * 32, sc = tyb * 32;
    const int tx = threadIdx.x, ty = threadIdx.y;
#pragma unroll
    for (int j = 0; j < 32; j += 8)
        t[ty + j][tx] = G[(size_t)(sr + ty + j) * EE + sc + tx];
    __syncthreads();
#pragma unroll
    for (int j = 0; j < 32; j += 8)
        G[(size_t)(sc + ty + j) * EE + sr + tx] = t[tx][ty + j];
}

// s[e] = sum_t X[t,e]   (atomic partials; s pre-zeroed)
__global__ __launch_bounds__(256)
void colsum_kernel(const float* __restrict__ X, float* __restrict__ s)
{
    const int e = blockIdx.x * 256 + threadIdx.x;
    const int t0 = blockIdx.y * (TT / 32);
    float acc = 0.f;
    for (int t = t0; t < t0 + TT / 32; t++) acc += X[(size_t)t * EE + e];
    atomicAdd(&s[e], acc);
}

// out[m] += sum_k W[k,m]*s[k]  (atomic partials; out pre-zeroed)
__global__ __launch_bounds__(256)
void gemv_tn(const float* __restrict__ W, const float* __restrict__ s,
             float* __restrict__ out)
{
    const int m = blockIdx.x * 256 + threadIdx.x;
    const int k0 = blockIdx.y * 256;
    float acc = 0.f;
    for (int k = k0; k < k0 + 256; k++) acc += W[(size_t)k * EE + m] * s[k];
    atomicAdd(&out[m], acc);
}

// out[m] = sum_e A[m,e]*x[e]   (warp per row)
__global__ __launch_bounds__(256)
void gemv_nn(const float* __restrict__ A, const float* __restrict__ x,
             float* __restrict__ out)
{
    const int row = blockIdx.x * 8 + (threadIdx.x >> 5);
    const int lane = threadIdx.x & 31;
    const float* p = A + (size_t)row * EE;
    float acc = 0.f;
    for (int e = lane; e < EE; e += 32) acc += p[e] * x[e];
#pragma unroll
    for (int o = 16; o > 0; o >>= 1) acc += __shfl_down_sync(~0u, acc, o);
    if (lane == 0) out[row] = acc;
}

// softmax rows with rank-1 bias terms:
// logit = S + u[row]*bk[col] + bq[row]*(w[col] + T*bk[col])
__global__ __launch_bounds__(256)
void softmax_rank1(float* __restrict__ S, const float* __restrict__ u,
                   const float* __restrict__ w, const float* __restrict__ bq,
                   const float* __restrict__ bk)
{
    __shared__ float buf[EE];
    __shared__ float red[256];
    const int row = blockIdx.x;
    const int tid = threadIdx.x;
    float* p = S + (size_t)row * EE;
    const float ur = u[row], br = bq[row];

    float lmax = -INFINITY;
    for (int i = tid; i < EE; i += 256) {
        float v = p[i] + ur * bk[i] + br * (w[i] + (float)TT * bk[i]);
        buf[i] = v;
        lmax = fmaxf(lmax, v);
    }
    red[tid] = lmax;
    __syncthreads();
#pragma unroll
    for (int s = 128; s > 0; s >>= 1) {
        if (tid < s) red[tid] = fmaxf(red[tid], red[tid + s]);
        __syncthreads();
    }
    const float m = red[0];
    __syncthreads();
    float lsum = 0.f;
    for (int i = tid; i < EE; i += 256) {
        float e = expf(buf[i] - m);
        buf[i] = e;
        lsum += e;
    }
    red[tid] = lsum;
    __syncthreads();
#pragma unroll
    for (int s = 128; s > 0; s >>= 1) {
        if (tid < s) red[tid] += red[tid + s];
        __syncthreads();
    }
    const float inv = 1.0f / red[0];
    for (int i = tid; i < EE; i += 256)
        p[i] = buf[i] * inv;
}

// ============================ host side =====================================
extern "C" void kernel_launch(void* const* d_in, const int* in_sizes, int n_in,
                              void* d_out, int out_size)
{
    const float* tokens = (const float*)d_in[0];
    const float* Wq = (const float*)d_in[1];
    const float* bq = (const float*)d_in[2];
    const float* Wk = (const float*)d_in[3];
    const float* bk = (const float*)d_in[4];
    const float* Wv = (const float*)d_in[5];
    const float* bv = (const float*)d_in[6];
    const float* Wp = (const float*)d_in[7];
    const float* bp = (const float*)d_in[8];
    float* out = (float*)d_out;

    unsigned char* base;
    cudaGetSymbolAddress((void**)&base, g_scratch);
#define PF(off) ((float*)(base + (off)))
#define PU(off) ((unsigned short*)(base + (off)))

    cudaFuncSetAttribute(hm_gemm<0,0,true,3>,  cudaFuncAttributeMaxDynamicSharedMemorySize, SMEM_BYTES);
    cudaFuncSetAttribute(hm_gemm<0,1,false,3>, cudaFuncAttributeMaxDynamicSharedMemorySize, SMEM_BYTES);
    cudaFuncSetAttribute(hm_gemm<0,0,false,3>, cudaFuncAttributeMaxDynamicSharedMemorySize, SMEM_BYTES);
    cudaFuncSetAttribute(hm_gemm<0,1,false,2>, cudaFuncAttributeMaxDynamicSharedMemorySize, SMEM_BYTES);
    cudaFuncSetAttribute(hm_gemm<2,1,false,2>, cudaFuncAttributeMaxDynamicSharedMemorySize, SMEM_BYTES);
    cudaFuncSetAttribute(hm_gemm<1,0,false,2>, cudaFuncAttributeMaxDynamicSharedMemorySize, SMEM_BYTES);

    const dim3 blk(256), tb(32, 8);
    float* s = PF(OFF_VS); float* u = PF(OFF_VU);
    float* w = PF(OFF_VW); float* r = PF(OFF_VR);

    // 0. zero s,u,w (atomic accumulators)
    cudaMemsetAsync(base + OFF_VS, 0, 49152);

    // 1. s = colsum(X) ; tokT split
    colsum_kernel<<<dim3(EE / 256, 32), blk>>>(tokens, s);
    split_tr<<<dim3(EE / 32, TT / 32), tb>>>(tokens, PU(OFF_TOKTH), PU(OFF_TOKTL), TT, EE);

    // 2. G = X^T X (lower triangle, 3-term), mirror, split
    hm_gemm<0,0,true,3><<<dim3(EE/128, EE/128), blk, SMEM_BYTES>>>(
        PU(OFF_TOKTH), PU(OFF_TOKTL), PU(OFF_TOKTH), PU(OFF_TOKTL),
        nullptr, nullptr, PF(OFF_GF), nullptr, nullptr, EE, TT);
    mirror_upper<<<dim3(EE/32, EE/32), tb>>>(PF(OFF_GF));
    {
        size_t n4 = (size_t)EE * EE / 4;
        split_dir<<<(unsigned)((n4 + 255) / 256), blk>>>(
            (const float4*)PF(OFF_GF), (ushort4*)PU(OFF_GH), (ushort4*)PU(OFF_GL), n4);
    }

    // 3. P1 = Wq^T G  (3-term, fused split out) ; u = Wq^T s
    split_tr<<<dim3(EE / 32, EE / 32), tb>>>(Wq, PU(OFF_WQTH), PU(OFF_WQTL), EE, EE);
    gemv_tn<<<dim3(EE / 256, EE / 256), blk>>>(Wq, s, u);
    hm_gemm<0,1,false,3><<<dim3(EE/128, EE/128), blk, SMEM_BYTES>>>(
        PU(OFF_WQTH), PU(OFF_WQTL), PU(OFF_GH), PU(OFF_GL),
        nullptr, nullptr, nullptr, PU(OFF_P1H), PU(OFF_P1L), EE, EE);

    // 4. S = P1 Wk (3-term) ; w = Wk^T s
    split_tr<<<dim3(EE / 32, EE / 32), tb>>>(Wk, PU(OFF_WKTH), PU(OFF_WKTL), EE, EE);
    gemv_tn<<<dim3(EE / 256, EE / 256), blk>>>(Wk, s, w);
    hm_gemm<0,0,false,3><<<dim3(EE/128, EE/128), blk, SMEM_BYTES>>>(
        PU(OFF_P1H), PU(OFF_P1L), PU(OFF_WKTH), PU(OFF_WKTL),
        nullptr, nullptr, PF(OFF_S), nullptr, nullptr, EE, EE);

    // 5. softmax (+rank-1 bias terms) ; r = att bv ; split att
    softmax_rank1<<<EE, blk>>>(PF(OFF_S), u, w, bq, bk);
    gemv_nn<<<EE / 8, blk>>>(PF(OFF_S), bv, r);
    {
        size_t n4 = (size_t)EE * EE / 4;
        split_dir<<<(unsigned)((n4 + 255) / 256), blk>>>(
            (const float4*)PF(OFF_S), (ushort4*)PU(OFF_ATH), (ushort4*)PU(OFF_ATL), n4);
    }

    // 6. U = att Wv^T (2-term, fused split out)
    {
        size_t n4 = (size_t)EE * EE / 4;
        split_dir<<<(unsigned)((n4 + 255) / 256), blk>>>(
            (const float4*)Wv, (ushort4*)PU(OFF_WVH), (ushort4*)PU(OFF_WVL), n4);
    }
    hm_gemm<0,1,false,2><<<dim3(EE/128, EE/128), blk, SMEM_BYTES>>>(
        PU(OFF_ATH), PU(OFF_ATL), PU(OFF_WVH), PU(OFF_WVL),
        nullptr, nullptr, nullptr, PU(OFF_UH), PU(OFF_UL), EE, EE);

    // 7. o = U X^T + r 1^T (2-term, fused split out)
    {
        size_t n4 = (size_t)TT * EE / 4;
        split_dir<<<(unsigned)((n4 + 255) / 256), blk>>>(
            (const float4*)tokens, (ushort4*)PU(OFF_TOKH), (ushort4*)PU(OFF_TOKL), n4);
    }
    hm_gemm<2,1,false,2><<<dim3(TT/128, EE/128), blk, SMEM_BYTES>>>(
        PU(OFF_UH), PU(OFF_UL), PU(OFF_TOKH), PU(OFF_TOKL),
        nullptr, r, nullptr, PU(OFF_OH), PU(OFF_OL), TT, EE);

    // 8. out = o Wp + bp (2-term)
    split_tr<<<dim3(TT / 32, TT / 32), tb>>>(Wp, PU(OFF_WPTH), PU(OFF_WPTL), TT, TT);
    hm_gemm<1,0,false,2><<<dim3(TT/128, EE/128), blk, SMEM_BYTES>>>(
        PU(OFF_OH), PU(OFF_OL), PU(OFF_WPTH), PU(OFF_WPTL),
        bp, nullptr, out, nullptr, nullptr, TT, TT);
#undef PF
#undef PU
}

// round 14
// speedup vs baseline: 5.8258x; 1.2182x over previous
#include <cuda_runtime.h>
#include <cuda_bf16.h>
#include <cuda_fp16.h>
#include <math.h>
#include <stdint.h>

#define TT 8192   // sequence length T
#define EE 4096   // embedding E

// ============================ scratch (576MB + vecs, reused) =================
static constexpr size_t MB = 1ull << 20;
// Pool A @0 (128MB): tokT h/l -> Gh/Gl + Uh/Ul -> WpTl
static constexpr size_t OFF_TOKTH = 0,      OFF_TOKTL = 64*MB;
static constexpr size_t OFF_GH    = 0,      OFF_GL    = 32*MB;
static constexpr size_t OFF_UH    = 64*MB,  OFF_UL    = 96*MB;
static constexpr size_t OFF_WPTL  = 0;
// Pool B @128 (64MB): G fp32 -> P1 h/l -> Wv h/l
static constexpr size_t OFF_GF    = 128*MB;
static constexpr size_t OFF_P1H   = 128*MB, OFF_P1L   = 160*MB;
static constexpr size_t OFF_WVH   = 128*MB, OFF_WVL   = 160*MB;
// Pool C @192 (64MB): WqT h/l -> WkT h/l -> att h/l
static constexpr size_t OFF_WQTH  = 192*MB, OFF_WQTL  = 224*MB;
static constexpr size_t OFF_WKTH  = 192*MB, OFF_WKTL  = 224*MB;
static constexpr size_t OFF_ATH   = 192*MB, OFF_ATL   = 224*MB;
// Pool D @256 (64MB): S fp32 / att fp32
static constexpr size_t OFF_S     = 256*MB;
// Pool E @320 (128MB): tok h/l -> WpTh
static constexpr size_t OFF_TOKH  = 320*MB, OFF_TOKL  = 384*MB;
static constexpr size_t OFF_WPTH  = 320*MB;
// Pool F @448 (128MB): o h/l
static constexpr size_t OFF_OH    = 448*MB, OFF_OL    = 512*MB;
// vectors
static constexpr size_t OFF_VS    = 576*MB;            // s [E]
static constexpr size_t OFF_VU    = 576*MB + 16384;    // u [E]
static constexpr size_t OFF_VW    = 576*MB + 32768;    // w [E]
static constexpr size_t OFF_VR    = 576*MB + 49152;    // r [E]
static constexpr size_t TOTAL_SCRATCH = 576*MB + 65536;
__device__ __align__(1024) unsigned char g_scratch[TOTAL_SCRATCH];

// ============================ PTX helpers ===================================
__device__ __forceinline__ uint32_t smem_u32(const void* p) {
    uint32_t a;
    asm("{ .reg .u64 t; cvta.to.shared.u64 t, %1; cvt.u32.u64 %0, t; }" : "=r"(a) : "l"(p));
    return a;
}
__device__ __forceinline__ void cp16(uint32_t s, const void* g) {
    asm volatile("cp.async.cg.shared.global [%0], [%1], 16;" :: "r"(s), "l"(g));
}
__device__ __forceinline__ void ldm_x4(uint32_t* r, uint32_t addr) {
    asm volatile("ldmatrix.sync.aligned.m8n8.x4.shared.b16 {%0,%1,%2,%3}, [%4];"
                 : "=r"(r[0]), "=r"(r[1]), "=r"(r[2]), "=r"(r[3]) : "r"(addr));
}
// fp16 inputs, fp32 accumulate
__device__ __forceinline__ void mma16816(float* c, const uint32_t* a, const uint32_t* b) {
    asm volatile(
        "mma.sync.aligned.m16n8k16.row.col.f32.f16.f16.f32 "
        "{%0,%1,%2,%3}, {%4,%5,%6,%7}, {%8,%9}, {%0,%1,%2,%3};"
        : "+f"(c[0]), "+f"(c[1]), "+f"(c[2]), "+f"(c[3])
        : "r"(a[0]), "r"(a[1]), "r"(a[2]), "r"(a[3]), "r"(b[0]), "r"(b[1]));
}

// fp16 hi/lo split
__device__ __forceinline__ void split1(float x, unsigned short& h, unsigned short& l) {
    __half hb = __float2half_rn(x);
    float r = x - __half2float(hb);
    __half lb = __float2half_rn(r);
    h = __half_as_ushort(hb);
    l = __half_as_ushort(lb);
}

// ============================ fp16-split GEMM (mma.sync) =====================
// C[M,N] = sum_k A[m,k]*B[n,k]; A,B fp16 hi/lo, K-major. Block 128x128x32,
// 256 threads, warp tile 64x32, 2-stage cp.async, 2 CTAs/SM.
// BMODE: 0 none, 1 col bias, 2 row bias.  OUT: 0 fp32, 1 hi/lo split.
// TRI: only bm>=bn blocks.
// NT: 3 = hh+hl+lh;  2 = hh+hl;  1 = hh only (lo arrays never loaded).
constexpr int BK = 32;
constexpr int ARR_BYTES = 128 * 80;
constexpr int STG_BYTES = 4 * ARR_BYTES;
constexpr int SMEM_BYTES = 2 * STG_BYTES;   // 81920

template <int BMODE, int OUT, bool TRI, int NT>
__global__ __launch_bounds__(256, 2)
void hm_gemm(const unsigned short* __restrict__ Ah, const unsigned short* __restrict__ Al,
             const unsigned short* __restrict__ Bh, const unsigned short* __restrict__ Bl,
             const float* __restrict__ cbias, const float* __restrict__ rbias,
             float* __restrict__ C,
             unsigned short* __restrict__ Chi, unsigned short* __restrict__ Clo,
             int Ntot, int Ktot)
{
    extern __shared__ __align__(128) char smem[];
    const uint32_t sb = smem_u32(smem);
    const int tid = threadIdx.x, lane = tid & 31, wid = tid >> 5;
    const int bm = blockIdx.y * 128, bn = blockIdx.x * 128;
    if (TRI && bm < bn) return;
    const int wm = (wid >> 2) * 64, wn = (wid & 3) * 32;
    const int nch = Ktot >> 5;

    const int r0 = tid >> 2;
    const int lc = (tid & 3) * 8;

    auto load_stage = [&](int stg, int ch) {
        const uint32_t st = sb + stg * STG_BYTES;
        const size_t ko = (size_t)(ch * BK) + lc;
        cp16(st + 0 * ARR_BYTES + (r0)      * 80 + lc * 2, Ah + (size_t)(bm + r0)      * Ktot + ko);
        cp16(st + 0 * ARR_BYTES + (r0 + 64) * 80 + lc * 2, Ah + (size_t)(bm + r0 + 64) * Ktot + ko);
        if (NT == 3) {
            cp16(st + 1 * ARR_BYTES + (r0)      * 80 + lc * 2, Al + (size_t)(bm + r0)      * Ktot + ko);
            cp16(st + 1 * ARR_BYTES + (r0 + 64) * 80 + lc * 2, Al + (size_t)(bm + r0 + 64) * Ktot + ko);
        }
        cp16(st + 2 * ARR_BYTES + (r0)      * 80 + lc * 2, Bh + (size_t)(bn + r0)      * Ktot + ko);
        cp16(st + 2 * ARR_BYTES + (r0 + 64) * 80 + lc * 2, Bh + (size_t)(bn + r0 + 64) * Ktot + ko);
        if (NT >= 2) {
            cp16(st + 3 * ARR_BYTES + (r0)      * 80 + lc * 2, Bl + (size_t)(bn + r0)      * Ktot + ko);
            cp16(st + 3 * ARR_BYTES + (r0 + 64) * 80 + lc * 2, Bl + (size_t)(bn + r0 + 64) * Ktot + ko);
        }
        asm volatile("cp.async.commit_group;");
    };

    const int sel = lane >> 3, r8 = lane & 7;
    const uint32_t aoffA = (uint32_t)((wm + (sel & 1) * 8 + r8) * 80 + (sel >> 1) * 16);
    const uint32_t aoffB = (uint32_t)((wn + (sel >> 1) * 8 + r8) * 80 + (sel & 1) * 16);

    float acc[4][4][4];
#pragma unroll
    for (int a = 0; a < 4; a++)
#pragma unroll
        for (int b = 0; b < 4; b++)
#pragma unroll
            for (int c = 0; c < 4; c++) acc[a][b][c] = 0.0f;

    load_stage(0, 0);
    if (nch > 1) load_stage(1, 1);

    for (int i = 0; i < nch; i++) {
        asm volatile("cp.async.wait_group 1;");
        __syncthreads();

        const uint32_t st = sb + (i & 1) * STG_BYTES;
        uint32_t af[4][4], bh[4][2], bl[4][2];

        // ---- k16 = 0 ----
        {
            const uint32_t ko = 0;
#pragma unroll
            for (int mt = 0; mt < 4; mt++)
                ldm_x4(af[mt], st + 0 * ARR_BYTES + aoffA + mt * 1280 + ko);
#pragma unroll
            for (int p = 0; p < 2; p++) {
                uint32_t t[4];
                ldm_x4(t, st + 2 * ARR_BYTES + aoffB + p * 1280 + ko);
                bh[2 * p][0] = t[0]; bh[2 * p][1] = t[1];
                bh[2 * p + 1][0] = t[2]; bh[2 * p + 1][1] = t[3];
                if (NT >= 2) {
                    ldm_x4(t, st + 3 * ARR_BYTES + aoffB + p * 1280 + ko);
                    bl[2 * p][0] = t[0]; bl[2 * p][1] = t[1];
                    bl[2 * p + 1][0] = t[2]; bl[2 * p + 1][1] = t[3];
                }
            }
#pragma unroll
            for (int mt = 0; mt < 4; mt++)
#pragma unroll
                for (int nt = 0; nt < 4; nt++)
                    mma16816(acc[mt][nt], af[mt], bh[nt]);
            if (NT >= 2) {
#pragma unroll
                for (int mt = 0; mt < 4; mt++)
#pragma unroll
                    for (int nt = 0; nt < 4; nt++)
                        mma16816(acc[mt][nt], af[mt], bl[nt]);
            }
            if (NT == 3) {
#pragma unroll
                for (int mt = 0; mt < 4; mt++)
                    ldm_x4(af[mt], st + 1 * ARR_BYTES + aoffA + mt * 1280 + ko);
#pragma unroll
                for (int mt = 0; mt < 4; mt++)
#pragma unroll
                    for (int nt = 0; nt < 4; nt++)
                        mma16816(acc[mt][nt], af[mt], bh[nt]);
            }
        }
        // ---- k16 = 1 ----
        {
            const uint32_t ko = 32;
#pragma unroll
            for (int mt = 0; mt < 4; mt++)
                ldm_x4(af[mt], st + 0 * ARR_BYTES + aoffA + mt * 1280 + ko);
#pragma unroll
            for (int p = 0; p < 2; p++) {
                uint32_t t[4];
                ldm_x4(t, st + 2 * ARR_BYTES + aoffB + p * 1280 + ko);
                bh[2 * p][0] = t[0]; bh[2 * p][1] = t[1];
                bh[2 * p + 1][0] = t[2]; bh[2 * p + 1][1] = t[3];
                if (NT >= 2) {
                    ldm_x4(t, st + 3 * ARR_BYTES + aoffB + p * 1280 + ko);
                    bl[2 * p][0] = t[0]; bl[2 * p][1] = t[1];
                    bl[2 * p + 1][0] = t[2]; bl[2 * p + 1][1] = t[3];
                }
            }
            if (NT == 3) {
#pragma unroll
                for (int mt = 0; mt < 4; mt++)
#pragma unroll
                    for (int nt = 0; nt < 4; nt++)
                        mma16816(acc[mt][nt], af[mt], bh[nt]);
#pragma unroll
                for (int mt = 0; mt < 4; mt++)
#pragma unroll
                    for (int nt = 0; nt < 4; nt++)
                        mma16816(acc[mt][nt], af[mt], bl[nt]);
#pragma unroll
                for (int mt = 0; mt < 4; mt++)
                    ldm_x4(af[mt], st + 1 * ARR_BYTES + aoffA + mt * 1280 + ko);
                __syncthreads();
#pragma unroll
                for (int mt = 0; mt < 4; mt++)
#pragma unroll
                    for (int nt = 0; nt < 4; nt++)
                        mma16816(acc[mt][nt], af[mt], bh[nt]);
            } else if (NT == 2) {
                __syncthreads();
#pragma unroll
                for (int mt = 0; mt < 4; mt++)
#pragma unroll
                    for (int nt = 0; nt < 4; nt++)
                        mma16816(acc[mt][nt], af[mt], bh[nt]);
#pragma unroll
                for (int mt = 0; mt < 4; mt++)
#pragma unroll
                    for (int nt = 0; nt < 4; nt++)
                        mma16816(acc[mt][nt], af[mt], bl[nt]);
            } else {
                __syncthreads();
#pragma unroll
                for (int mt = 0; mt < 4; mt++)
#pragma unroll
                    for (int nt = 0; nt < 4; nt++)
                        mma16816(acc[mt][nt], af[mt], bh[nt]);
            }
        }
        if (i + 2 < nch) load_stage(i & 1, i + 2);
    }

    // ---- epilogue ----
    const int g = lane >> 2, tg = lane & 3;
#pragma unroll
    for (int mt = 0; mt < 4; mt++) {
#pragma unroll
        for (int nt = 0; nt < 4; nt++) {
            const int m = bm + wm + mt * 16 + g;
            const int n = bn + wn + nt * 8 + tg * 2;
            float c0 = 0.f, c1 = 0.f, rr0 = 0.f, rr1 = 0.f;
            if (BMODE == 1) { c0 = cbias[n]; c1 = cbias[n + 1]; }
            if (BMODE == 2) { rr0 = rbias[m]; rr1 = rbias[m + 8]; }
            float v00 = acc[mt][nt][0] + c0 + rr0, v01 = acc[mt][nt][1] + c1 + rr0;
            float v10 = acc[mt][nt][2] + c0 + rr1, v11 = acc[mt][nt][3] + c1 + rr1;
            if (OUT == 0) {
                *reinterpret_cast<float2*>(&C[(size_t)m * Ntot + n]) = make_float2(v00, v01);
                *reinterpret_cast<float2*>(&C[(size_t)(m + 8) * Ntot + n]) = make_float2(v10, v11);
            } else {
                ushort2 h0, l0, h1, l1;
                split1(v00, h0.x, l0.x); split1(v01, h0.y, l0.y);
                split1(v10, h1.x, l1.x); split1(v11, h1.y, l1.y);
                *reinterpret_cast<ushort2*>(&Chi[(size_t)m * Ntot + n]) = h0;
                *reinterpret_cast<ushort2*>(&Clo[(size_t)m * Ntot + n]) = l0;
                *reinterpret_cast<ushort2*>(&Chi[(size_t)(m + 8) * Ntot + n]) = h1;
                *reinterpret_cast<ushort2*>(&Clo[(size_t)(m + 8) * Ntot + n]) = l1;
            }
        }
    }
}

// ============================ aux kernels ===================================
__global__ __launch_bounds__(256)
void split_dir(const float4* __restrict__ x, ushort4* __restrict__ hi,
               ushort4* __restrict__ lo, size_t n4)
{
    size_t i = (size_t)blockIdx.x * blockDim.x + threadIdx.x;
    if (i >= n4) return;
    float4 v = x[i];
    ushort4 h, l;
    split1(v.x, h.x, l.x); split1(v.y, h.y, l.y);
    split1(v.z, h.z, l.z); split1(v.w, h.w, l.w);
    hi[i] = h; lo[i] = l;
}

// X [R,C] fp32 -> hi/lo [C,R] fp16   (launch with (32,8) block!)
__global__ __launch_bounds__(256)
void split_tr(const float* __restrict__ x, unsigned short* __restrict__ hi,
              unsigned short* __restrict__ lo, int R, int C)
{
    __shared__ float t[32][33];
    const int c0 = blockIdx.x * 32, r0 = blockIdx.y * 32;
    const int tx = threadIdx.x, ty = threadIdx.y;
#pragma unroll
    for (int j = 0; j < 32; j += 8)
        t[ty + j][tx] = x[(size_t)(r0 + ty + j) * C + c0 + tx];
    __syncthreads();
#pragma unroll
    for (int j = 0; j < 32; j += 8) {
        float v = t[tx][ty + j];
        unsigned short h, l;
        split1(v, h, l);
        size_t o = (size_t)(c0 + ty + j) * R + r0 + tx;
        hi[o] = h; lo[o] = l;
    }
}

// mirror lower triangle of G to upper (32x32 tiles; (32,8) block!)
__global__ __launch_bounds__(256)
void mirror_upper(float* __restrict__ G)
{
    const int txb = blockIdx.x, tyb = blockIdx.y;
    if (txb <= tyb) return;
    __shared__ float t[32][33];
    const int sr = txb * 32, sc = tyb * 32;
    const int tx = threadIdx.x, ty = threadIdx.y;
#pragma unroll
    for (int j = 0; j < 32; j += 8)
        t[ty + j][tx] = G[(size_t)(sr + ty + j) * EE + sc + tx];
    __syncthreads();
#pragma unroll
    for (int j = 0; j < 32; j += 8)
        G[(size_t)(sc + ty + j) * EE + sr + tx] = t[tx][ty + j];
}

__global__ __launch_bounds__(256)
void colsum_kernel(const float* __restrict__ X, float* __restrict__ s)
{
    const int e = blockIdx.x * 256 + threadIdx.x;
    const int t0 = blockIdx.y * (TT / 32);
    float acc = 0.f;
    for (int t = t0; t < t0 + TT / 32; t++) acc += X[(size_t)t * EE + e];
    atomicAdd(&s[e], acc);
}

__global__ __launch_bounds__(256)
void gemv_tn(const float* __restrict__ W, const float* __restrict__ s,
             float* __restrict__ out)
{
    const int m = blockIdx.x * 256 + threadIdx.x;
    const int k0 = blockIdx.y * 256;
    float acc = 0.f;
    for (int k = k0; k < k0 + 256; k++) acc += W[(size_t)k * EE + m] * s[k];
    atomicAdd(&out[m], acc);
}

__global__ __launch_bounds__(256)
void gemv_nn(const float* __restrict__ A, const float* __restrict__ x,
             float* __restrict__ out)
{
    const int row = blockIdx.x * 8 + (threadIdx.x >> 5);
    const int lane = threadIdx.x & 31;
    const float* p = A + (size_t)row * EE;
    float acc = 0.f;
    for (int e = lane; e < EE; e += 32) acc += p[e] * x[e];
#pragma unroll
    for (int o = 16; o > 0; o >>= 1) acc += __shfl_down_sync(~0u, acc, o);
    if (lane == 0) out[row] = acc;
}

// softmax rows with rank-1 bias terms
__global__ __launch_bounds__(256)
void softmax_rank1(float* __restrict__ S, const float* __restrict__ u,
                   const float* __restrict__ w, const float* __restrict__ bq,
                   const float* __restrict__ bk)
{
    __shared__ float buf[EE];
    __shared__ float red[256];
    const int row = blockIdx.x;
    const int tid = threadIdx.x;
    float* p = S + (size_t)row * EE;
    const float ur = u[row], br = bq[row];

    float lmax = -INFINITY;
    for (int i = tid; i < EE; i += 256) {
        float v = p[i] + ur * bk[i] + br * (w[i] + (float)TT * bk[i]);
        buf[i] = v;
        lmax = fmaxf(lmax, v);
    }
    red[tid] = lmax;
    __syncthreads();
#pragma unroll
    for (int s = 128; s > 0; s >>= 1) {
        if (tid < s) red[tid] = fmaxf(red[tid], red[tid + s]);
        __syncthreads();
    }
    const float m = red[0];
    __syncthreads();
    float lsum = 0.f;
    for (int i = tid; i < EE; i += 256) {
        float e = expf(buf[i] - m);
        buf[i] = e;
        lsum += e;
    }
    red[tid] = lsum;
    __syncthreads();
#pragma unroll
    for (int s = 128; s > 0; s >>= 1) {
        if (tid < s) red[tid] += red[tid + s];
        __syncthreads();
    }
    const float inv = 1.0f / red[0];
    for (int i = tid; i < EE; i += 256)
        p[i] = buf[i] * inv;
}

// ============================ host side =====================================
extern "C" void kernel_launch(void* const* d_in, const int* in_sizes, int n_in,
                              void* d_out, int out_size)
{
    const float* tokens = (const float*)d_in[0];
    const float* Wq = (const float*)d_in[1];
    const float* bq = (const float*)d_in[2];
    const float* Wk = (const float*)d_in[3];
    const float* bk = (const float*)d_in[4];
    const float* Wv = (const float*)d_in[5];
    const float* bv = (const float*)d_in[6];
    const float* Wp = (const float*)d_in[7];
    const float* bp = (const float*)d_in[8];
    float* out = (float*)d_out;

    unsigned char* base;
    cudaGetSymbolAddress((void**)&base, g_scratch);
#define PF(off) ((float*)(base + (off)))
#define PU(off) ((unsigned short*)(base + (off)))

    cudaFuncSetAttribute(hm_gemm<0,0,true,3>,  cudaFuncAttributeMaxDynamicSharedMemorySize, SMEM_BYTES);
    cudaFuncSetAttribute(hm_gemm<0,1,false,3>, cudaFuncAttributeMaxDynamicSharedMemorySize, SMEM_BYTES);
    cudaFuncSetAttribute(hm_gemm<0,0,false,3>, cudaFuncAttributeMaxDynamicSharedMemorySize, SMEM_BYTES);
    cudaFuncSetAttribute(hm_gemm<2,1,false,1>, cudaFuncAttributeMaxDynamicSharedMemorySize, SMEM_BYTES);
    cudaFuncSetAttribute(hm_gemm<1,0,false,1>, cudaFuncAttributeMaxDynamicSharedMemorySize, SMEM_BYTES);

    const dim3 blk(256), tb(32, 8);
    float* s = PF(OFF_VS); float* u = PF(OFF_VU);
    float* w = PF(OFF_VW); float* r = PF(OFF_VR);

    // 0. zero s,u,w (atomic accumulators)
    cudaMemsetAsync(base + OFF_VS, 0, 49152);

    // 1. s = colsum(X) ; tokT split
    colsum_kernel<<<dim3(EE / 256, 32), blk>>>(tokens, s);
    split_tr<<<dim3(EE / 32, TT / 32), tb>>>(tokens, PU(OFF_TOKTH), PU(OFF_TOKTL), TT, EE);

    // 2. G = X^T X (lower triangle, 3-term), mirror, split
    hm_gemm<0,0,true,3><<<dim3(EE/128, EE/128), blk, SMEM_BYTES>>>(
        PU(OFF_TOKTH), PU(OFF_TOKTL), PU(OFF_TOKTH), PU(OFF_TOKTL),
        nullptr, nullptr, PF(OFF_GF), nullptr, nullptr, EE, TT);
    mirror_upper<<<dim3(EE/32, EE/32), tb>>>(PF(OFF_GF));
    {
        size_t n4 = (size_t)EE * EE / 4;
        split_dir<<<(unsigned)((n4 + 255) / 256), blk>>>(
            (const float4*)PF(OFF_GF), (ushort4*)PU(OFF_GH), (ushort4*)PU(OFF_GL), n4);
    }

    // 3. P1 = Wq^T G  (3-term, fused split out) ; u = Wq^T s
    split_tr<<<dim3(EE / 32, EE / 32), tb>>>(Wq, PU(OFF_WQTH), PU(OFF_WQTL), EE, EE);
    gemv_tn<<<dim3(EE / 256, EE / 256), blk>>>(Wq, s, u);
    hm_gemm<0,1,false,3><<<dim3(EE/128, EE/128), blk, SMEM_BYTES>>>(
        PU(OFF_WQTH), PU(OFF_WQTL), PU(OFF_GH), PU(OFF_GL),
        nullptr, nullptr, nullptr, PU(OFF_P1H), PU(OFF_P1L), EE, EE);

    // 4. S = P1 Wk (3-term) ; w = Wk^T s
    split_tr<<<dim3(EE / 32, EE / 32), tb>>>(Wk, PU(OFF_WKTH), PU(OFF_WKTL), EE, EE);
    gemv_tn<<<dim3(EE / 256, EE / 256), blk>>>(Wk, s, w);
    hm_gemm<0,0,false,3><<<dim3(EE/128, EE/128), blk, SMEM_BYTES>>>(
        PU(OFF_P1H), PU(OFF_P1L), PU(OFF_WKTH), PU(OFF_WKTL),
        nullptr, nullptr, PF(OFF_S), nullptr, nullptr, EE, EE);

    // 5. softmax (+rank-1 bias terms) ; r = att bv ; split att
    softmax_rank1<<<EE, blk>>>(PF(OFF_S), u, w, bq, bk);
    gemv_nn<<<EE / 8, blk>>>(PF(OFF_S), bv, r);
    {
        size_t n4 = (size_t)EE * EE / 4;
        split_dir<<<(unsigned)((n4 + 255) / 256), blk>>>(
            (const float4*)PF(OFF_S), (ushort4*)PU(OFF_ATH), (ushort4*)PU(OFF_ATL), n4);
    }

    // 6. U = att Wv^T (3-term: att-lo carries subnormal attention weights)
    {
        size_t n4 = (size_t)EE * EE / 4;
        split_dir<<<(unsigned)((n4 + 255) / 256), blk>>>(
            (const float4*)Wv, (ushort4*)PU(OFF_WVH), (ushort4*)PU(OFF_WVL), n4);
    }
    hm_gemm<0,1,false,3><<<dim3(EE/128, EE/128), blk, SMEM_BYTES>>>(
        PU(OFF_ATH), PU(OFF_ATL), PU(OFF_WVH), PU(OFF_WVL),
        nullptr, nullptr, nullptr, PU(OFF_UH), PU(OFF_UL), EE, EE);

    // 7. o = U X^T + r 1^T (1-term hh, fused split out)
    {
        size_t n4 = (size_t)TT * EE / 4;
        split_dir<<<(unsigned)((n4 + 255) / 256), blk>>>(
            (const float4*)tokens, (ushort4*)PU(OFF_TOKH), (ushort4*)PU(OFF_TOKL), n4);
    }
    hm_gemm<2,1,false,1><<<dim3(TT/128, EE/128), blk, SMEM_BYTES>>>(
        PU(OFF_UH), PU(OFF_UL), PU(OFF_TOKH), PU(OFF_TOKL),
        nullptr, r, nullptr, PU(OFF_OH), PU(OFF_OL), TT, EE);

    // 8. out = o Wp + bp (1-term hh)
    split_tr<<<dim3(TT / 32, TT / 32), tb>>>(Wp, PU(OFF_WPTH), PU(OFF_WPTL), TT, TT);
    hm_gemm<1,0,false,1><<<dim3(TT/128, EE/128), blk, SMEM_BYTES>>>(
        PU(OFF_OH), PU(OFF_OL), PU(OFF_WPTH), PU(OFF_WPTL),
        bp, nullptr, out, nullptr, nullptr, TT, TT);
#undef PF
#undef PU
}